// round 7
// baseline (speedup 1.0000x reference)
#include <cuda_runtime.h>
#include <cuda_bf16.h>
#include <cstdint>

// ---------------------------------------------------------------------------
// KronFTLinear, bf16 mma.sync GEMMs, tiered precision:
//   * base GEMM (full output magnitude)   -> bf16x3 split (fp32-like)
//   * delta path (only ~2.5e-2 of output) -> pure bf16 (errors attenuated 40x)
// GEMM engine: 128x256x32 CTA tile, 8 warps (64x64 warp tile), 3-stage
// cp.async pipeline, mma.sync m16n8k16 (HMMA on sm_103 base target).
// ---------------------------------------------------------------------------

#define DD 4096
#define OO 4096
#define HALF_D 2048
#define NFP 1000
#define ROWS 8192
#define NGATE 819
#define K3 (3*DD)        // 12288 (base GEMM split-K)

typedef long long ll;

// ---------------- device scratch (no allocation allowed) -------------------
__device__ int   g_idx32[2*NFP];
__device__ int   g_gidx32[NGATE];
__device__ float g_gate_m[2*DD];
__device__ float g_gate_w[ROWS*2];
__device__ __nv_bfloat16 g_Pms[2ll*HALF_D*HALF_D];  // trig A-factor [p][m][k]
__device__ __nv_bfloat16 g_Qns[2ll*HALF_D*HALF_D];  // trig B-factor [p][n][k]
__device__ __nv_bfloat16 g_W2s[(ll)HALF_D*DD];      // A-matrix stack bf16
__device__ __nv_bfloat16 g_Zs[2ll*ROWS*DD];         // gated mixed x bf16
__device__ __nv_bfloat16 g_xs[(ll)ROWS*K3];         // split x  [xh|xl|xh]
__device__ __nv_bfloat16 g_ws[(ll)OO*K3];           // split base_w [wh|wh|wl]

// ---------------- PTX helpers ----------------------------------------------
__device__ __forceinline__ uint32_t smem_u32(const void* p) {
    uint32_t a;
    asm("{ .reg .u64 t; cvta.to.shared.u64 t, %1; cvt.u32.u64 %0, t; }" : "=r"(a) : "l"(p));
    return a;
}
#define CP_ASYNC16(dst, src) \
    asm volatile("cp.async.cg.shared.global [%0], [%1], 16;" :: "r"(dst), "l"(src) : "memory")
#define CP_COMMIT() asm volatile("cp.async.commit_group;" ::: "memory")

#define LDSM_X4(r0, r1, r2, r3, addr) \
    asm volatile("ldmatrix.sync.aligned.m8n8.x4.shared.b16 {%0,%1,%2,%3}, [%4];" \
        : "=r"(r0), "=r"(r1), "=r"(r2), "=r"(r3) : "r"(addr))

#define MMA16816(c, a, b) \
    asm volatile("mma.sync.aligned.m16n8k16.row.col.f32.bf16.bf16.f32 " \
        "{%0,%1,%2,%3}, {%4,%5,%6,%7}, {%8,%9}, {%0,%1,%2,%3};" \
        : "+f"((c)[0]), "+f"((c)[1]), "+f"((c)[2]), "+f"((c)[3]) \
        : "r"((a)[0]), "r"((a)[1]), "r"((a)[2]), "r"((a)[3]), \
          "r"((b)[0]), "r"((b)[1]))

// ---------------- index decode: sniff int32 vs int64 -----------------------
__global__ void k_decode_idx(const int* __restrict__ idx_raw,
                             const int* __restrict__ gidx_raw) {
    __shared__ int nz;
    if (threadIdx.x == 0) nz = 0;
    __syncthreads();
    for (int k = threadIdx.x; k < NFP/2; k += 256)
        if (idx_raw[2*k + 1] != 0) atomicAdd(&nz, 1);
    __syncthreads();
    bool is64 = (nz == 0);
    for (int k = threadIdx.x; k < 2*NFP; k += 256)
        g_idx32[k] = is64 ? idx_raw[2*k] : idx_raw[k];
    for (int k = threadIdx.x; k < NGATE; k += 256)
        g_gidx32[k] = is64 ? gidx_raw[2*k] : gidx_raw[k];
}

// ---------------- gate matrix ----------------------------------------------
__global__ void k_gate_m(const float* __restrict__ gate_param) {
    __shared__ float tab[DD];
    __shared__ int   gc[NGATE];
    __shared__ float gg[NGATE], gs[NGATE];
    for (int t = threadIdx.x; t < DD; t += 256)
        tab[t] = cospif(t * (1.0f/2048.0f));
    for (int k = threadIdx.x; k < NGATE; k += 256) {
        int v = g_gidx32[k];
        int r = v >> 12;
        gc[k] = v & 4095;
        float g = gate_param[k];
        gg[k] = g;
        gs[k] = r ? -g : g;
    }
    __syncthreads();
    int d = blockIdx.x * 256 + threadIdx.x;
    float a0 = 0.f, a1 = 0.f;
    for (int k = 0; k < NGATE; k++) {
        int t = (d * gc[k]) & 4095;
        float co = tab[t];
        a0 += gg[k] * co;
        a1 += gs[k] * co;
    }
    g_gate_m[d]      = a0 * (1.0f/8192.0f);
    g_gate_m[DD + d] = a1 * (1.0f/8192.0f);
}

// ---------------- gate weights ---------------------------------------------
__global__ void k_gate_w(const float* __restrict__ x) {
    int row = blockIdx.x;
    const float* xr = x + (ll)row * DD;
    float t0 = 0.f, t1 = 0.f;
    for (int d = threadIdx.x; d < DD; d += 128) {
        float xv = xr[d];
        t0 += xv * g_gate_m[d];
        t1 += xv * g_gate_m[DD + d];
    }
    __shared__ float s0[128], s1[128];
    s0[threadIdx.x] = t0; s1[threadIdx.x] = t1;
    __syncthreads();
    for (int o = 64; o > 0; o >>= 1) {
        if (threadIdx.x < o) {
            s0[threadIdx.x] += s0[threadIdx.x + o];
            s1[threadIdx.x] += s1[threadIdx.x + o];
        }
        __syncthreads();
    }
    if (threadIdx.x == 0) {
        float g1 = 1.0f / (1.0f + expf(-(s1[0] - s0[0])));
        g_gate_w[row*2 + 0] = 1.0f - g1;
        g_gate_w[row*2 + 1] = g1;
    }
}

// ---------------- trig factors, plain bf16 ---------------------------------
__global__ void k_fill_trig(const float* __restrict__ spectrum) {
    __shared__ float tc[HALF_D], ts[HALF_D];
    __shared__ int   rr[NFP], cc[NFP];
    __shared__ float ss[NFP];
    int p = blockIdx.y;
    for (int t = threadIdx.x; t < HALF_D; t += 256) {
        float s, c;
        sincospif(t * (1.0f/1024.0f), &s, &c);
        tc[t] = c; ts[t] = s;
    }
    for (int k = threadIdx.x; k < NFP; k += 256) {
        int v = g_idx32[p*NFP + k];
        rr[k] = v >> 11;
        cc[k] = v & 2047;
        ss[k] = spectrum[p*NFP + k];
    }
    __syncthreads();
    int v0 = blockIdx.x * 8;
    for (int vi = 0; vi < 8; vi++) {
        int v = v0 + vi;
        ll base = ((ll)(p*HALF_D + v)) * HALF_D;
        for (int k = threadIdx.x; k < NFP; k += 256) {
            int tm = (v * rr[k]) & 2047;
            int tn = (v * cc[k]) & 2047;
            float s = ss[k];
            g_Pms[base + k]       = __float2bfloat16(s * tc[tm]);
            g_Pms[base + NFP + k] = __float2bfloat16(s * ts[tm]);
            g_Qns[base + k]       = __float2bfloat16(tc[tn]);
            g_Qns[base + NFP + k] = __float2bfloat16(-ts[tn]);
        }
        for (int k = 2*NFP + threadIdx.x; k < HALF_D; k += 256) {
            __nv_bfloat16 z = __float2bfloat16(0.f);
            g_Pms[base + k] = z;
            g_Qns[base + k] = z;
        }
    }
}

// ---------------- fp32 -> split bf16 (rows of 4096, base GEMM only) --------
__global__ void k_split(const float* __restrict__ src, __nv_bfloat16* __restrict__ dst,
                        ll n, int hi2blk, int loblk) {
    ll i = (ll)blockIdx.x * 256 + threadIdx.x;
    if (i >= n) return;
    ll m = i >> 12;
    int k = (int)(i & 4095);
    float v = src[i];
    __nv_bfloat16 h = __float2bfloat16(v);
    __nv_bfloat16 l = __float2bfloat16(v - __bfloat162float(h));
    ll base = m * K3;
    dst[base + k] = h;
    dst[base + (ll)hi2blk*DD + k] = h;
    dst[base + (ll)loblk*DD + k]  = l;
}

// ---------------- Z build, plain bf16 --------------------------------------
__global__ void k_build_z(const float* __restrict__ x, const float* __restrict__ Blist) {
    ll gid = (ll)blockIdx.x * 256 + threadIdx.x;
    int row = (int)(gid >> 11);
    int d2  = (int)(gid & 2047);
    float2 xv = ((const float2*)x)[(ll)row * HALF_D + d2];
    float g0 = g_gate_w[row*2 + 0];
    float g1 = g_gate_w[row*2 + 1];
    float y00 = g0 * (Blist[0]*xv.x + Blist[1]*xv.y);   // i=0, p=0
    float y01 = g0 * (Blist[2]*xv.x + Blist[3]*xv.y);   // i=1, p=0
    float y10 = g1 * (Blist[4]*xv.x + Blist[5]*xv.y);   // i=0, p=1
    float y11 = g1 * (Blist[6]*xv.x + Blist[7]*xv.y);   // i=1, p=1
    const ll IOFF = (ll)ROWS * DD;
    ll b0 = (ll)row * DD;
    g_Zs[b0 + d2]                 = __float2bfloat16(y00);
    g_Zs[b0 + HALF_D + d2]        = __float2bfloat16(y10);
    g_Zs[IOFF + b0 + d2]          = __float2bfloat16(y01);
    g_Zs[IOFF + b0 + HALF_D + d2] = __float2bfloat16(y11);
}

// ---------------- bf16 tensor-core GEMM: C = alpha * A @ B^T (+bias)(+=C) --
// 128x256x32 CTA tile, 8 warps (2x4), warp tile 64x64, 3-stage cp.async.
// A:[M x Kp] bf16 row-major, B:[N x Kp] bf16 row-major.
// Output element (m,n,z) at C[m*ldc + n*cstride + z*czoff]; fp32 or bf16.
#define A_STG 10240u           // 128 rows * 80B
#define B_STG 20480u           // 256 rows * 80B
#define SMEM_DYN (3*(A_STG + B_STG))   // 92160 B

__global__ __launch_bounds__(256, 1)
void tgemm(const __nv_bfloat16* __restrict__ A, int lda, ll sAz,
           const __nv_bfloat16* __restrict__ B, int ldb, ll sBz,
           void* __restrict__ Cv, int ldc, int cstride, int czoff,
           const float* __restrict__ bias, float alpha, int accumulate,
           int Kp, int out_bf16)
{
    extern __shared__ char smem[];
    uint32_t aB = smem_u32(smem);
    uint32_t bB = aB + 3*A_STG;
    int tid = threadIdx.x, wid = tid >> 5, lane = tid & 31;
    int warpM = wid >> 2;          // 0..1  (64 rows)
    int warpN = wid & 3;           // 0..3  (64 cols)
    int z = blockIdx.z;
    ll m0 = (ll)blockIdx.x * 128;
    ll n0 = (ll)blockIdx.y * 256;
    const __nv_bfloat16* Ab = A + (ll)z*sAz + m0*lda;
    const __nv_bfloat16* Bb = B + (ll)z*sBz + n0*ldb;

    float acc[4][8][4];
    #pragma unroll
    for (int i = 0; i < 4; i++)
        #pragma unroll
        for (int j = 0; j < 8; j++)
            #pragma unroll
            for (int q = 0; q < 4; q++) acc[i][j][q] = 0.f;

    int ldr = tid >> 2;            // 0..63
    int ldc8 = (tid & 3) * 8;      // 0,8,16,24

    int aRow = warpM*64 + (lane & 15);
    int aCsel = (lane >> 4) * 8;
    int bRowOff = (lane & 7) + ((lane >> 4) << 3);
    int bCsel = ((lane >> 3) & 1) * 8;

    int NP = Kp >> 5;

    // pipeline issue for K-chunk kc into stage kc%3
    #define TG_ISSUE(kc) do {                                                  \
        int _k0 = (kc) * 32;                                                   \
        uint32_t _s = (uint32_t)((kc) % 3);                                    \
        uint32_t _da = aB + _s*A_STG + (uint32_t)ldr*80 + (uint32_t)ldc8*2;    \
        CP_ASYNC16(_da,          Ab + (ll)ldr*lda + _k0 + ldc8);               \
        CP_ASYNC16(_da + 64*80,  Ab + (ll)(ldr+64)*lda + _k0 + ldc8);          \
        uint32_t _db = bB + _s*B_STG + (uint32_t)ldr*80 + (uint32_t)ldc8*2;    \
        CP_ASYNC16(_db,           Bb + (ll)ldr*ldb + _k0 + ldc8);              \
        CP_ASYNC16(_db + 64*80,   Bb + (ll)(ldr+64)*ldb + _k0 + ldc8);         \
        CP_ASYNC16(_db + 128*80,  Bb + (ll)(ldr+128)*ldb + _k0 + ldc8);        \
        CP_ASYNC16(_db + 192*80,  Bb + (ll)(ldr+192)*ldb + _k0 + ldc8);        \
        CP_COMMIT();                                                           \
    } while (0)

    TG_ISSUE(0);
    if (NP > 1) TG_ISSUE(1);

    for (int kc = 0; kc < NP; kc++) {
        asm volatile("cp.async.wait_group 1;" ::: "memory");
        __syncthreads();
        if (kc + 2 < NP) TG_ISSUE(kc + 2);

        uint32_t sao = aB + (uint32_t)(kc % 3) * A_STG;
        uint32_t sbo = bB + (uint32_t)(kc % 3) * B_STG;
        #pragma unroll
        for (int ks = 0; ks < 32; ks += 16) {
            uint32_t af[4][4];
            #pragma unroll
            for (int mi = 0; mi < 4; mi++) {
                uint32_t ad = sao + (uint32_t)(aRow + mi*16)*80 + (uint32_t)(ks + aCsel)*2;
                LDSM_X4(af[mi][0], af[mi][1], af[mi][2], af[mi][3], ad);
            }
            uint32_t bf[8][2];
            #pragma unroll
            for (int nj = 0; nj < 4; nj++) {
                uint32_t bd = sbo + (uint32_t)(warpN*64 + nj*16 + bRowOff)*80
                                  + (uint32_t)(ks + bCsel)*2;
                uint32_t r0, r1, r2, r3;
                LDSM_X4(r0, r1, r2, r3, bd);
                bf[nj*2][0] = r0;   bf[nj*2][1] = r1;
                bf[nj*2+1][0] = r2; bf[nj*2+1][1] = r3;
            }
            #pragma unroll
            for (int mi = 0; mi < 4; mi++)
                #pragma unroll
                for (int ni = 0; ni < 8; ni++)
                    MMA16816(acc[mi][ni], af[mi], bf[ni]);
        }
    }

    // epilogue
    int gID = lane >> 2, tig = lane & 3;
    #pragma unroll
    for (int mi = 0; mi < 4; mi++) {
        #pragma unroll
        for (int h = 0; h < 2; h++) {
            ll row = m0 + warpM*64 + mi*16 + gID + h*8;
            ll rbase = row * (ll)ldc + (ll)z * czoff;
            #pragma unroll
            for (int ni = 0; ni < 8; ni++) {
                ll col0 = n0 + warpN*64 + ni*8 + tig*2;
                #pragma unroll
                for (int q = 0; q < 2; q++) {
                    ll col = col0 + q;
                    float v = acc[mi][ni][h*2 + q] * alpha;
                    if (bias) v += bias[col];
                    ll off = rbase + col * cstride;
                    if (out_bf16) {
                        ((__nv_bfloat16*)Cv)[off] = __float2bfloat16(v);
                    } else {
                        float* cp = (float*)Cv + off;
                        if (accumulate) v += *cp;
                        *cp = v;
                    }
                }
            }
        }
    }
    #undef TG_ISSUE
}

// ---------------------------------------------------------------------------
extern "C" void kernel_launch(void* const* d_in, const int* in_sizes, int n_in,
                              void* d_out, int out_size) {
    const float* x          = (const float*)d_in[0];
    const float* base_w     = (const float*)d_in[1];
    const float* base_b     = (const float*)d_in[2];
    const float* spectrum   = (const float*)d_in[3];
    const float* Blist      = (const float*)d_in[4];
    const float* gate_param = (const float*)d_in[5];
    const int*   idx_raw    = (const int*)d_in[6];
    const int*   gidx_raw   = (const int*)d_in[7];
    float* out = (float*)d_out;
    (void)in_sizes; (void)n_in; (void)out_size;

    __nv_bfloat16 *pPms, *pQns, *pW2s, *pZs, *pxs, *pws;
    cudaGetSymbolAddress((void**)&pPms, g_Pms);
    cudaGetSymbolAddress((void**)&pQns, g_Qns);
    cudaGetSymbolAddress((void**)&pW2s, g_W2s);
    cudaGetSymbolAddress((void**)&pZs,  g_Zs);
    cudaGetSymbolAddress((void**)&pxs,  g_xs);
    cudaGetSymbolAddress((void**)&pws,  g_ws);

    cudaFuncSetAttribute(tgemm, cudaFuncAttributeMaxDynamicSharedMemorySize, SMEM_DYN);

    // 0..3: small prep
    k_decode_idx<<<1, 256>>>(idx_raw, gidx_raw);
    k_gate_m<<<16, 256>>>(gate_param);
    k_gate_w<<<ROWS, 128>>>(x);
    k_fill_trig<<<dim3(256, 2), 256>>>(spectrum);

    // 4. A_p = (1/2048^2) * Pm @ Qn^T -> bf16 W2s[o2][p*2048+d2]  (K=2048)
    tgemm<<<dim3(16, 8, 2), 256, SMEM_DYN>>>(
        pPms, HALF_D, (ll)HALF_D*HALF_D,
        pQns, HALF_D, (ll)HALF_D*HALF_D,
        pW2s, DD, 1, HALF_D,
        nullptr, 1.0f/4194304.0f, 0, HALF_D, 1);

    // 5. splits + Z (base GEMM operands split, delta operands plain bf16)
    k_build_z<<<(ROWS*HALF_D)/256, 256>>>(x, Blist);
    k_split<<<(int)(((ll)ROWS*DD + 255)/256), 256>>>(x,      pxs, (ll)ROWS*DD, 2, 1);
    k_split<<<(int)(((ll)OO*DD + 255)/256), 256>>>(base_w,   pws, (ll)OO*DD, 1, 2);

    // 6. delta: out[row, 2n+z] = 150 * (Z_z @ W2s^T)  M=8192, N=2048, K=4096
    tgemm<<<dim3(64, 8, 2), 256, SMEM_DYN>>>(
        pZs, DD, (ll)ROWS*DD,
        pW2s, DD, 0ll,
        out, OO, 2, 1,
        nullptr, 150.0f, 0, DD, 0);

    // 7. base: out += x @ W^T + b   M=8192, N=4096, K'=12288 (bf16x3 split)
    tgemm<<<dim3(64, 16, 1), 256, SMEM_DYN>>>(
        pxs, K3, 0ll,
        pws, K3, 0ll,
        out, OO, 1, 0,
        base_b, 1.0f, 1, K3, 0);
}

// round 8
// speedup vs baseline: 1.0699x; 1.0699x over previous
#include <cuda_runtime.h>
#include <cuda_bf16.h>
#include <cstdint>

// ---------------------------------------------------------------------------
// KronFTLinear, bf16 mma.sync GEMMs, tiered precision:
//   * base GEMM (full output magnitude)   -> bf16x3 split (fp32-like)
//   * delta path (only ~2.5e-2 of output) -> pure bf16 (errors attenuated 40x)
// GEMM engine (R6 winner): 128x128x32 CTA tile, 8 warps (64x32 warp tile),
// double-buffered cp.async, 2 CTAs/SM.  R8 adds an L2-friendly CTA raster
// swizzle (groups of 8 m-tiles sweep all n-tiles -> A slab stays in L2).
// ---------------------------------------------------------------------------

#define DD 4096
#define OO 4096
#define HALF_D 2048
#define NFP 1000
#define ROWS 8192
#define NGATE 819
#define K3 (3*DD)        // 12288 (base GEMM split-K)

typedef long long ll;

// ---------------- device scratch (no allocation allowed) -------------------
__device__ int   g_idx32[2*NFP];
__device__ int   g_gidx32[NGATE];
__device__ float g_gate_m[2*DD];
__device__ float g_gate_w[ROWS*2];
__device__ __nv_bfloat16 g_Pms[2ll*HALF_D*HALF_D];  // trig A-factor [p][m][k]
__device__ __nv_bfloat16 g_Qns[2ll*HALF_D*HALF_D];  // trig B-factor [p][n][k]
__device__ __nv_bfloat16 g_W2s[(ll)HALF_D*DD];      // A-matrix stack bf16
__device__ __nv_bfloat16 g_Zs[2ll*ROWS*DD];         // gated mixed x bf16
__device__ __nv_bfloat16 g_xs[(ll)ROWS*K3];         // split x  [xh|xl|xh]
__device__ __nv_bfloat16 g_ws[(ll)OO*K3];           // split base_w [wh|wh|wl]

// ---------------- PTX helpers ----------------------------------------------
__device__ __forceinline__ uint32_t smem_u32(const void* p) {
    uint32_t a;
    asm("{ .reg .u64 t; cvta.to.shared.u64 t, %1; cvt.u32.u64 %0, t; }" : "=r"(a) : "l"(p));
    return a;
}
#define CP_ASYNC16(dst, src) \
    asm volatile("cp.async.cg.shared.global [%0], [%1], 16;" :: "r"(dst), "l"(src) : "memory")
#define CP_COMMIT() asm volatile("cp.async.commit_group;" ::: "memory")

#define LDSM_X4(r0, r1, r2, r3, addr) \
    asm volatile("ldmatrix.sync.aligned.m8n8.x4.shared.b16 {%0,%1,%2,%3}, [%4];" \
        : "=r"(r0), "=r"(r1), "=r"(r2), "=r"(r3) : "r"(addr))

#define MMA16816(c, a, b) \
    asm volatile("mma.sync.aligned.m16n8k16.row.col.f32.bf16.bf16.f32 " \
        "{%0,%1,%2,%3}, {%4,%5,%6,%7}, {%8,%9}, {%0,%1,%2,%3};" \
        : "+f"((c)[0]), "+f"((c)[1]), "+f"((c)[2]), "+f"((c)[3]) \
        : "r"((a)[0]), "r"((a)[1]), "r"((a)[2]), "r"((a)[3]), \
          "r"((b)[0]), "r"((b)[1]))

// ---------------- index decode: sniff int32 vs int64 -----------------------
__global__ void k_decode_idx(const int* __restrict__ idx_raw,
                             const int* __restrict__ gidx_raw) {
    __shared__ int nz;
    if (threadIdx.x == 0) nz = 0;
    __syncthreads();
    for (int k = threadIdx.x; k < NFP/2; k += 256)
        if (idx_raw[2*k + 1] != 0) atomicAdd(&nz, 1);
    __syncthreads();
    bool is64 = (nz == 0);
    for (int k = threadIdx.x; k < 2*NFP; k += 256)
        g_idx32[k] = is64 ? idx_raw[2*k] : idx_raw[k];
    for (int k = threadIdx.x; k < NGATE; k += 256)
        g_gidx32[k] = is64 ? gidx_raw[2*k] : gidx_raw[k];
}

// ---------------- gate matrix ----------------------------------------------
__global__ void k_gate_m(const float* __restrict__ gate_param) {
    __shared__ float tab[DD];
    __shared__ int   gc[NGATE];
    __shared__ float gg[NGATE], gs[NGATE];
    for (int t = threadIdx.x; t < DD; t += 256)
        tab[t] = cospif(t * (1.0f/2048.0f));
    for (int k = threadIdx.x; k < NGATE; k += 256) {
        int v = g_gidx32[k];
        int r = v >> 12;
        gc[k] = v & 4095;
        float g = gate_param[k];
        gg[k] = g;
        gs[k] = r ? -g : g;
    }
    __syncthreads();
    int d = blockIdx.x * 256 + threadIdx.x;
    float a0 = 0.f, a1 = 0.f;
    for (int k = 0; k < NGATE; k++) {
        int t = (d * gc[k]) & 4095;
        float co = tab[t];
        a0 += gg[k] * co;
        a1 += gs[k] * co;
    }
    g_gate_m[d]      = a0 * (1.0f/8192.0f);
    g_gate_m[DD + d] = a1 * (1.0f/8192.0f);
}

// ---------------- gate weights ---------------------------------------------
__global__ void k_gate_w(const float* __restrict__ x) {
    int row = blockIdx.x;
    const float* xr = x + (ll)row * DD;
    float t0 = 0.f, t1 = 0.f;
    for (int d = threadIdx.x; d < DD; d += 128) {
        float xv = xr[d];
        t0 += xv * g_gate_m[d];
        t1 += xv * g_gate_m[DD + d];
    }
    __shared__ float s0[128], s1[128];
    s0[threadIdx.x] = t0; s1[threadIdx.x] = t1;
    __syncthreads();
    for (int o = 64; o > 0; o >>= 1) {
        if (threadIdx.x < o) {
            s0[threadIdx.x] += s0[threadIdx.x + o];
            s1[threadIdx.x] += s1[threadIdx.x + o];
        }
        __syncthreads();
    }
    if (threadIdx.x == 0) {
        float g1 = 1.0f / (1.0f + expf(-(s1[0] - s0[0])));
        g_gate_w[row*2 + 0] = 1.0f - g1;
        g_gate_w[row*2 + 1] = g1;
    }
}

// ---------------- trig factors, plain bf16 ---------------------------------
__global__ void k_fill_trig(const float* __restrict__ spectrum) {
    __shared__ float tc[HALF_D], ts[HALF_D];
    __shared__ int   rr[NFP], cc[NFP];
    __shared__ float ss[NFP];
    int p = blockIdx.y;
    for (int t = threadIdx.x; t < HALF_D; t += 256) {
        float s, c;
        sincospif(t * (1.0f/1024.0f), &s, &c);
        tc[t] = c; ts[t] = s;
    }
    for (int k = threadIdx.x; k < NFP; k += 256) {
        int v = g_idx32[p*NFP + k];
        rr[k] = v >> 11;
        cc[k] = v & 2047;
        ss[k] = spectrum[p*NFP + k];
    }
    __syncthreads();
    int v0 = blockIdx.x * 8;
    for (int vi = 0; vi < 8; vi++) {
        int v = v0 + vi;
        ll base = ((ll)(p*HALF_D + v)) * HALF_D;
        for (int k = threadIdx.x; k < NFP; k += 256) {
            int tm = (v * rr[k]) & 2047;
            int tn = (v * cc[k]) & 2047;
            float s = ss[k];
            g_Pms[base + k]       = __float2bfloat16(s * tc[tm]);
            g_Pms[base + NFP + k] = __float2bfloat16(s * ts[tm]);
            g_Qns[base + k]       = __float2bfloat16(tc[tn]);
            g_Qns[base + NFP + k] = __float2bfloat16(-ts[tn]);
        }
        for (int k = 2*NFP + threadIdx.x; k < HALF_D; k += 256) {
            __nv_bfloat16 z = __float2bfloat16(0.f);
            g_Pms[base + k] = z;
            g_Qns[base + k] = z;
        }
    }
}

// ---------------- fp32 -> split bf16 (rows of 4096, base GEMM only) --------
__global__ void k_split(const float* __restrict__ src, __nv_bfloat16* __restrict__ dst,
                        ll n, int hi2blk, int loblk) {
    ll i = (ll)blockIdx.x * 256 + threadIdx.x;
    if (i >= n) return;
    ll m = i >> 12;
    int k = (int)(i & 4095);
    float v = src[i];
    __nv_bfloat16 h = __float2bfloat16(v);
    __nv_bfloat16 l = __float2bfloat16(v - __bfloat162float(h));
    ll base = m * K3;
    dst[base + k] = h;
    dst[base + (ll)hi2blk*DD + k] = h;
    dst[base + (ll)loblk*DD + k]  = l;
}

// ---------------- Z build, plain bf16 --------------------------------------
__global__ void k_build_z(const float* __restrict__ x, const float* __restrict__ Blist) {
    ll gid = (ll)blockIdx.x * 256 + threadIdx.x;
    int row = (int)(gid >> 11);
    int d2  = (int)(gid & 2047);
    float2 xv = ((const float2*)x)[(ll)row * HALF_D + d2];
    float g0 = g_gate_w[row*2 + 0];
    float g1 = g_gate_w[row*2 + 1];
    float y00 = g0 * (Blist[0]*xv.x + Blist[1]*xv.y);   // i=0, p=0
    float y01 = g0 * (Blist[2]*xv.x + Blist[3]*xv.y);   // i=1, p=0
    float y10 = g1 * (Blist[4]*xv.x + Blist[5]*xv.y);   // i=0, p=1
    float y11 = g1 * (Blist[6]*xv.x + Blist[7]*xv.y);   // i=1, p=1
    const ll IOFF = (ll)ROWS * DD;
    ll b0 = (ll)row * DD;
    g_Zs[b0 + d2]                 = __float2bfloat16(y00);
    g_Zs[b0 + HALF_D + d2]        = __float2bfloat16(y10);
    g_Zs[IOFF + b0 + d2]          = __float2bfloat16(y01);
    g_Zs[IOFF + b0 + HALF_D + d2] = __float2bfloat16(y11);
}

// ---------------- bf16 tensor-core GEMM: C = alpha * A @ B^T (+bias)(+=C) --
// 128x128x32 CTA tile, 8 warps (64x32 warp tile), cp.async double buffer,
// 2 CTAs/SM.  CTA raster swizzle: groups of GRP m-tiles sweep all n-tiles
// so the A slab (GRP*128 rows x K) stays resident in L2 across the sweep.
// Output element (m,n,z) at C[m*ldc + n*cstride + z*czoff]; fp32 or bf16.
#define ASTR 40                // smem row stride in bf16 (80B, conflict-free)
#define STG_B (128*ASTR)       // bf16 elems per stage
#define GRP 8                  // m-tiles per L2 group (all grid.x % 8 == 0)

__global__ __launch_bounds__(256, 2)
void tgemm(const __nv_bfloat16* __restrict__ A, int lda, ll sAz,
           const __nv_bfloat16* __restrict__ B, int ldb, ll sBz,
           void* __restrict__ Cv, int ldc, int cstride, int czoff,
           const float* __restrict__ bias, float alpha, int accumulate,
           int Kp, int out_bf16)
{
    __shared__ __nv_bfloat16 sA[2*STG_B];
    __shared__ __nv_bfloat16 sB[2*STG_B];
    uint32_t aB = smem_u32(sA), bB = smem_u32(sB);
    int tid = threadIdx.x, wid = tid >> 5, lane = tid & 31;
    int warpM = wid >> 2;          // 0..1  (64 rows)
    int warpN = wid & 3;           // 0..3  (32 cols)
    int z = blockIdx.z;

    // L2 raster swizzle: bid -> (m-tile, n-tile), m-group of GRP sweeps all n
    int bid = blockIdx.y * gridDim.x + blockIdx.x;   // x fastest = launch order
    int tpg = GRP * gridDim.y;
    int grp = bid / tpg;
    int rem = bid - grp * tpg;
    int mt  = grp * GRP + (rem % GRP);
    int nt  = rem / GRP;

    ll m0 = (ll)mt * 128;
    ll n0 = (ll)nt * 128;
    const __nv_bfloat16* Ab = A + (ll)z*sAz + m0*lda;
    const __nv_bfloat16* Bb = B + (ll)z*sBz + n0*ldb;

    float acc[4][4][4];
    #pragma unroll
    for (int i = 0; i < 4; i++)
        #pragma unroll
        for (int j = 0; j < 4; j++)
            #pragma unroll
            for (int q = 0; q < 4; q++) acc[i][j][q] = 0.f;

    int ldr = tid >> 2;
    int ldc8 = (tid & 3) * 8;

    int aRow = warpM*64 + (lane & 15);
    int aCsel = (lane >> 4) * 8;
    int bRowOff = (lane & 7) + ((lane >> 4) << 3);
    int bCsel = ((lane >> 3) & 1) * 8;

    int NP = Kp >> 5;

    {
        uint32_t da = aB + ldr*80 + ldc8*2;
        uint32_t db = bB + ldr*80 + ldc8*2;
        CP_ASYNC16(da,        Ab + (ll)ldr*lda + ldc8);
        CP_ASYNC16(db,        Bb + (ll)ldr*ldb + ldc8);
        CP_ASYNC16(da + 64*80, Ab + (ll)(ldr+64)*lda + ldc8);
        CP_ASYNC16(db + 64*80, Bb + (ll)(ldr+64)*ldb + ldc8);
        CP_COMMIT();
    }

    for (int kc = 0; kc < NP; kc++) {
        int st = kc & 1;
        if (kc + 1 < NP) {
            int k0 = (kc + 1) * 32;
            uint32_t so = ((kc + 1) & 1) * (STG_B*2);
            uint32_t da = aB + so + ldr*80 + ldc8*2;
            uint32_t db = bB + so + ldr*80 + ldc8*2;
            CP_ASYNC16(da,        Ab + (ll)ldr*lda + k0 + ldc8);
            CP_ASYNC16(db,        Bb + (ll)ldr*ldb + k0 + ldc8);
            CP_ASYNC16(da + 64*80, Ab + (ll)(ldr+64)*lda + k0 + ldc8);
            CP_ASYNC16(db + 64*80, Bb + (ll)(ldr+64)*ldb + k0 + ldc8);
            CP_COMMIT();
            asm volatile("cp.async.wait_group 1;" ::: "memory");
        } else {
            asm volatile("cp.async.wait_group 0;" ::: "memory");
        }
        __syncthreads();

        uint32_t sao = aB + st * (STG_B*2);
        uint32_t sbo = bB + st * (STG_B*2);
        #pragma unroll
        for (int ks = 0; ks < 32; ks += 16) {
            uint32_t af[4][4];
            #pragma unroll
            for (int mi = 0; mi < 4; mi++) {
                uint32_t ad = sao + (uint32_t)(aRow + mi*16)*80 + (uint32_t)(ks + aCsel)*2;
                LDSM_X4(af[mi][0], af[mi][1], af[mi][2], af[mi][3], ad);
            }
            uint32_t bf[4][2];
            #pragma unroll
            for (int nj = 0; nj < 2; nj++) {
                uint32_t bd = sbo + (uint32_t)(warpN*32 + nj*16 + bRowOff)*80
                                  + (uint32_t)(ks + bCsel)*2;
                uint32_t r0, r1, r2, r3;
                LDSM_X4(r0, r1, r2, r3, bd);
                bf[nj*2][0] = r0; bf[nj*2][1] = r1;
                bf[nj*2+1][0] = r2; bf[nj*2+1][1] = r3;
            }
            #pragma unroll
            for (int mi = 0; mi < 4; mi++)
                #pragma unroll
                for (int ni = 0; ni < 4; ni++)
                    MMA16816(acc[mi][ni], af[mi], bf[ni]);
        }
        __syncthreads();
    }

    // epilogue
    int gID = lane >> 2, tig = lane & 3;
    #pragma unroll
    for (int mi = 0; mi < 4; mi++) {
        #pragma unroll
        for (int h = 0; h < 2; h++) {
            ll row = m0 + warpM*64 + mi*16 + gID + h*8;
            ll rbase = row * (ll)ldc + (ll)z * czoff;
            #pragma unroll
            for (int ni = 0; ni < 4; ni++) {
                ll col0 = n0 + warpN*32 + ni*8 + tig*2;
                #pragma unroll
                for (int q = 0; q < 2; q++) {
                    ll col = col0 + q;
                    float v = acc[mi][ni][h*2 + q] * alpha;
                    if (bias) v += bias[col];
                    ll off = rbase + col * cstride;
                    if (out_bf16) {
                        ((__nv_bfloat16*)Cv)[off] = __float2bfloat16(v);
                    } else {
                        float* cp = (float*)Cv + off;
                        if (accumulate) v += *cp;
                        *cp = v;
                    }
                }
            }
        }
    }
}

// ---------------------------------------------------------------------------
extern "C" void kernel_launch(void* const* d_in, const int* in_sizes, int n_in,
                              void* d_out, int out_size) {
    const float* x          = (const float*)d_in[0];
    const float* base_w     = (const float*)d_in[1];
    const float* base_b     = (const float*)d_in[2];
    const float* spectrum   = (const float*)d_in[3];
    const float* Blist      = (const float*)d_in[4];
    const float* gate_param = (const float*)d_in[5];
    const int*   idx_raw    = (const int*)d_in[6];
    const int*   gidx_raw   = (const int*)d_in[7];
    float* out = (float*)d_out;
    (void)in_sizes; (void)n_in; (void)out_size;

    __nv_bfloat16 *pPms, *pQns, *pW2s, *pZs, *pxs, *pws;
    cudaGetSymbolAddress((void**)&pPms, g_Pms);
    cudaGetSymbolAddress((void**)&pQns, g_Qns);
    cudaGetSymbolAddress((void**)&pW2s, g_W2s);
    cudaGetSymbolAddress((void**)&pZs,  g_Zs);
    cudaGetSymbolAddress((void**)&pxs,  g_xs);
    cudaGetSymbolAddress((void**)&pws,  g_ws);

    // 0..3: small prep
    k_decode_idx<<<1, 256>>>(idx_raw, gidx_raw);
    k_gate_m<<<16, 256>>>(gate_param);
    k_gate_w<<<ROWS, 128>>>(x);
    k_fill_trig<<<dim3(256, 2), 256>>>(spectrum);

    // 4. A_p = (1/2048^2) * Pm @ Qn^T -> bf16 W2s[o2][p*2048+d2]  (K=2048)
    tgemm<<<dim3(16, 16, 2), 256>>>(
        pPms, HALF_D, (ll)HALF_D*HALF_D,
        pQns, HALF_D, (ll)HALF_D*HALF_D,
        pW2s, DD, 1, HALF_D,
        nullptr, 1.0f/4194304.0f, 0, HALF_D, 1);

    // 5. splits + Z (base GEMM operands split, delta operands plain bf16)
    k_build_z<<<(ROWS*HALF_D)/256, 256>>>(x, Blist);
    k_split<<<(int)(((ll)ROWS*DD + 255)/256), 256>>>(x,      pxs, (ll)ROWS*DD, 2, 1);
    k_split<<<(int)(((ll)OO*DD + 255)/256), 256>>>(base_w,   pws, (ll)OO*DD, 1, 2);

    // 6. delta: out[row, 2n+z] = 150 * (Z_z @ W2s^T)  M=8192, N=2048, K=4096
    tgemm<<<dim3(64, 16, 2), 256>>>(
        pZs, DD, (ll)ROWS*DD,
        pW2s, DD, 0ll,
        out, OO, 2, 1,
        nullptr, 150.0f, 0, DD, 0);

    // 7. base: out += x @ W^T + b   M=8192, N=4096, K'=12288 (bf16x3 split)
    tgemm<<<dim3(64, 32, 1), 256>>>(
        pxs, K3, 0ll,
        pws, K3, 0ll,
        out, OO, 1, 0,
        base_b, 1.0f, 1, K3, 0);
}

// round 9
// speedup vs baseline: 1.3463x; 1.2584x over previous
#include <cuda_runtime.h>
#include <cuda_fp16.h>
#include <cstdint>

// ---------------------------------------------------------------------------
// KronFTLinear, fp16 mma.sync GEMMs (m16n8k16, f32 accum), tiered precision:
//   * base GEMM: 2-term fp16 split  out = (xh + xl) @ wh  (+bias)
//       missing x*wl term -> ~2.8e-4 output rel err (fp16 ulp on w)
//   * delta path (~2.5e-2 of output magnitude): plain fp16 (error ~7e-6)
//   * trig-GEMM scale 150 folded into stored W2 (keeps fp16 normal range)
// GEMM engine: 128x128x32 CTA tile, 8 warps (64x32), cp.async double buffer,
// 2 CTAs/SM, L2 raster swizzle.
// ---------------------------------------------------------------------------

#define DD 4096
#define OO 4096
#define HALF_D 2048
#define NFP 1000
#define ROWS 8192
#define NGATE 819

typedef long long ll;

// ---------------- device scratch (no allocation allowed) -------------------
__device__ int   g_idx32[2*NFP];
__device__ int   g_gidx32[NGATE];
__device__ float g_gate_m[2*DD];
__device__ float g_gate_w[ROWS*2];
__device__ __half g_Pms[2ll*HALF_D*HALF_D];  // trig A-factor [p][m][k]
__device__ __half g_Qns[2ll*HALF_D*HALF_D];  // trig B-factor [p][n][k]
__device__ __half g_W2s[(ll)HALF_D*DD];      // 150 * A-matrix stack (fp16)
__device__ __half g_Zs[2ll*ROWS*DD];         // gated mixed x (fp16)
__device__ __half g_xh[(ll)ROWS*DD];         // fp16 hi part of x
__device__ __half g_xl[(ll)ROWS*DD];         // fp16 lo part of x
__device__ __half g_wh[(ll)OO*DD];           // fp16 base_w

// ---------------- PTX helpers ----------------------------------------------
__device__ __forceinline__ uint32_t smem_u32(const void* p) {
    uint32_t a;
    asm("{ .reg .u64 t; cvta.to.shared.u64 t, %1; cvt.u32.u64 %0, t; }" : "=r"(a) : "l"(p));
    return a;
}
#define CP_ASYNC16(dst, src) \
    asm volatile("cp.async.cg.shared.global [%0], [%1], 16;" :: "r"(dst), "l"(src) : "memory")
#define CP_COMMIT() asm volatile("cp.async.commit_group;" ::: "memory")

#define LDSM_X4(r0, r1, r2, r3, addr) \
    asm volatile("ldmatrix.sync.aligned.m8n8.x4.shared.b16 {%0,%1,%2,%3}, [%4];" \
        : "=r"(r0), "=r"(r1), "=r"(r2), "=r"(r3) : "r"(addr))

#define MMA16816(c, a, b) \
    asm volatile("mma.sync.aligned.m16n8k16.row.col.f32.f16.f16.f32 " \
        "{%0,%1,%2,%3}, {%4,%5,%6,%7}, {%8,%9}, {%0,%1,%2,%3};" \
        : "+f"((c)[0]), "+f"((c)[1]), "+f"((c)[2]), "+f"((c)[3]) \
        : "r"((a)[0]), "r"((a)[1]), "r"((a)[2]), "r"((a)[3]), \
          "r"((b)[0]), "r"((b)[1]))

// ---------------- index decode: sniff int32 vs int64 -----------------------
__global__ void k_decode_idx(const int* __restrict__ idx_raw,
                             const int* __restrict__ gidx_raw) {
    __shared__ int nz;
    if (threadIdx.x == 0) nz = 0;
    __syncthreads();
    for (int k = threadIdx.x; k < NFP/2; k += 256)
        if (idx_raw[2*k + 1] != 0) atomicAdd(&nz, 1);
    __syncthreads();
    bool is64 = (nz == 0);
    for (int k = threadIdx.x; k < 2*NFP; k += 256)
        g_idx32[k] = is64 ? idx_raw[2*k] : idx_raw[k];
    for (int k = threadIdx.x; k < NGATE; k += 256)
        g_gidx32[k] = is64 ? gidx_raw[2*k] : gidx_raw[k];
}

// ---------------- gate matrix ----------------------------------------------
__global__ void k_gate_m(const float* __restrict__ gate_param) {
    __shared__ float tab[DD];
    __shared__ int   gc[NGATE];
    __shared__ float gg[NGATE], gs[NGATE];
    for (int t = threadIdx.x; t < DD; t += 256)
        tab[t] = cospif(t * (1.0f/2048.0f));
    for (int k = threadIdx.x; k < NGATE; k += 256) {
        int v = g_gidx32[k];
        int r = v >> 12;
        gc[k] = v & 4095;
        float g = gate_param[k];
        gg[k] = g;
        gs[k] = r ? -g : g;
    }
    __syncthreads();
    int d = blockIdx.x * 256 + threadIdx.x;
    float a0 = 0.f, a1 = 0.f;
    for (int k = 0; k < NGATE; k++) {
        int t = (d * gc[k]) & 4095;
        float co = tab[t];
        a0 += gg[k] * co;
        a1 += gs[k] * co;
    }
    g_gate_m[d]      = a0 * (1.0f/8192.0f);
    g_gate_m[DD + d] = a1 * (1.0f/8192.0f);
}

// ---------------- gate weights ---------------------------------------------
__global__ void k_gate_w(const float* __restrict__ x) {
    int row = blockIdx.x;
    const float* xr = x + (ll)row * DD;
    float t0 = 0.f, t1 = 0.f;
    for (int d = threadIdx.x; d < DD; d += 128) {
        float xv = xr[d];
        t0 += xv * g_gate_m[d];
        t1 += xv * g_gate_m[DD + d];
    }
    __shared__ float s0[128], s1[128];
    s0[threadIdx.x] = t0; s1[threadIdx.x] = t1;
    __syncthreads();
    for (int o = 64; o > 0; o >>= 1) {
        if (threadIdx.x < o) {
            s0[threadIdx.x] += s0[threadIdx.x + o];
            s1[threadIdx.x] += s1[threadIdx.x + o];
        }
        __syncthreads();
    }
    if (threadIdx.x == 0) {
        float g1 = 1.0f / (1.0f + expf(-(s1[0] - s0[0])));
        g_gate_w[row*2 + 0] = 1.0f - g1;
        g_gate_w[row*2 + 1] = g1;
    }
}

// ---------------- trig factors, fp16 ----------------------------------------
__global__ void k_fill_trig(const float* __restrict__ spectrum) {
    __shared__ float tc[HALF_D], ts[HALF_D];
    __shared__ int   rr[NFP], cc[NFP];
    __shared__ float ss[NFP];
    int p = blockIdx.y;
    for (int t = threadIdx.x; t < HALF_D; t += 256) {
        float s, c;
        sincospif(t * (1.0f/1024.0f), &s, &c);
        tc[t] = c; ts[t] = s;
    }
    for (int k = threadIdx.x; k < NFP; k += 256) {
        int v = g_idx32[p*NFP + k];
        rr[k] = v >> 11;
        cc[k] = v & 2047;
        ss[k] = spectrum[p*NFP + k];
    }
    __syncthreads();
    int v0 = blockIdx.x * 8;
    for (int vi = 0; vi < 8; vi++) {
        int v = v0 + vi;
        ll base = ((ll)(p*HALF_D + v)) * HALF_D;
        for (int k = threadIdx.x; k < NFP; k += 256) {
            int tm = (v * rr[k]) & 2047;
            int tn = (v * cc[k]) & 2047;
            float s = ss[k];
            g_Pms[base + k]       = __float2half(s * tc[tm]);
            g_Pms[base + NFP + k] = __float2half(s * ts[tm]);
            g_Qns[base + k]       = __float2half(tc[tn]);
            g_Qns[base + NFP + k] = __float2half(-ts[tn]);
        }
        for (int k = 2*NFP + threadIdx.x; k < HALF_D; k += 256) {
            __half z = __float2half(0.f);
            g_Pms[base + k] = z;
            g_Qns[base + k] = z;
        }
    }
}

// ---------------- fp32 x -> fp16 hi/lo parts (separate buffers) ------------
__global__ void k_split_x(const float* __restrict__ src) {
    ll i = (ll)blockIdx.x * 256 + threadIdx.x;
    float v = src[i];
    __half h = __float2half(v);
    g_xh[i] = h;
    g_xl[i] = __float2half(v - __half2float(h));
}

// ---------------- fp32 w -> fp16 -------------------------------------------
__global__ void k_cast_w(const float* __restrict__ src) {
    ll i = (ll)blockIdx.x * 256 + threadIdx.x;
    g_wh[i] = __float2half(src[i]);
}

// ---------------- Z build, fp16 ---------------------------------------------
__global__ void k_build_z(const float* __restrict__ x, const float* __restrict__ Blist) {
    ll gid = (ll)blockIdx.x * 256 + threadIdx.x;
    int row = (int)(gid >> 11);
    int d2  = (int)(gid & 2047);
    float2 xv = ((const float2*)x)[(ll)row * HALF_D + d2];
    float g0 = g_gate_w[row*2 + 0];
    float g1 = g_gate_w[row*2 + 1];
    float y00 = g0 * (Blist[0]*xv.x + Blist[1]*xv.y);   // i=0, p=0
    float y01 = g0 * (Blist[2]*xv.x + Blist[3]*xv.y);   // i=1, p=0
    float y10 = g1 * (Blist[4]*xv.x + Blist[5]*xv.y);   // i=0, p=1
    float y11 = g1 * (Blist[6]*xv.x + Blist[7]*xv.y);   // i=1, p=1
    const ll IOFF = (ll)ROWS * DD;
    ll b0 = (ll)row * DD;
    g_Zs[b0 + d2]                 = __float2half(y00);
    g_Zs[b0 + HALF_D + d2]        = __float2half(y10);
    g_Zs[IOFF + b0 + d2]          = __float2half(y01);
    g_Zs[IOFF + b0 + HALF_D + d2] = __float2half(y11);
}

// ---------------- fp16 tensor-core GEMM: C = alpha * A @ B^T (+bias)(+=C) --
// 128x128x32 CTA tile, 8 warps (64x32 warp tile), cp.async double buffer,
// 2 CTAs/SM, L2 raster swizzle (GRP m-tiles sweep all n-tiles).
// Output element (m,n,z) at C[m*ldc + n*cstride + z*czoff]; fp32 or fp16.
#define ASTR 40                // smem row stride in halves (80B, conflict-free)
#define STG_B (128*ASTR)       // half elems per stage
#define GRP 8                  // m-tiles per L2 group (all grid.x % 8 == 0)

__global__ __launch_bounds__(256, 2)
void tgemm(const __half* __restrict__ A, int lda, ll sAz,
           const __half* __restrict__ B, int ldb, ll sBz,
           void* __restrict__ Cv, int ldc, int cstride, int czoff,
           const float* __restrict__ bias, float alpha, int accumulate,
           int Kp, int out_half)
{
    __shared__ __half sA[2*STG_B];
    __shared__ __half sB[2*STG_B];
    uint32_t aB = smem_u32(sA), bB = smem_u32(sB);
    int tid = threadIdx.x, wid = tid >> 5, lane = tid & 31;
    int warpM = wid >> 2;          // 0..1  (64 rows)
    int warpN = wid & 3;           // 0..3  (32 cols)
    int z = blockIdx.z;

    // L2 raster swizzle
    int bid = blockIdx.y * gridDim.x + blockIdx.x;
    int tpg = GRP * gridDim.y;
    int grp = bid / tpg;
    int rem = bid - grp * tpg;
    int mt  = grp * GRP + (rem % GRP);
    int nt  = rem / GRP;

    ll m0 = (ll)mt * 128;
    ll n0 = (ll)nt * 128;
    const __half* Ab = A + (ll)z*sAz + m0*lda;
    const __half* Bb = B + (ll)z*sBz + n0*ldb;

    float acc[4][4][4];
    #pragma unroll
    for (int i = 0; i < 4; i++)
        #pragma unroll
        for (int j = 0; j < 4; j++)
            #pragma unroll
            for (int q = 0; q < 4; q++) acc[i][j][q] = 0.f;

    int ldr = tid >> 2;
    int ldc8 = (tid & 3) * 8;

    int aRow = warpM*64 + (lane & 15);
    int aCsel = (lane >> 4) * 8;
    int bRowOff = (lane & 7) + ((lane >> 4) << 3);
    int bCsel = ((lane >> 3) & 1) * 8;

    int NP = Kp >> 5;

    {
        uint32_t da = aB + ldr*80 + ldc8*2;
        uint32_t db = bB + ldr*80 + ldc8*2;
        CP_ASYNC16(da,        Ab + (ll)ldr*lda + ldc8);
        CP_ASYNC16(db,        Bb + (ll)ldr*ldb + ldc8);
        CP_ASYNC16(da + 64*80, Ab + (ll)(ldr+64)*lda + ldc8);
        CP_ASYNC16(db + 64*80, Bb + (ll)(ldr+64)*ldb + ldc8);
        CP_COMMIT();
    }

    for (int kc = 0; kc < NP; kc++) {
        int st = kc & 1;
        if (kc + 1 < NP) {
            int k0 = (kc + 1) * 32;
            uint32_t so = ((kc + 1) & 1) * (STG_B*2);
            uint32_t da = aB + so + ldr*80 + ldc8*2;
            uint32_t db = bB + so + ldr*80 + ldc8*2;
            CP_ASYNC16(da,        Ab + (ll)ldr*lda + k0 + ldc8);
            CP_ASYNC16(db,        Bb + (ll)ldr*ldb + k0 + ldc8);
            CP_ASYNC16(da + 64*80, Ab + (ll)(ldr+64)*lda + k0 + ldc8);
            CP_ASYNC16(db + 64*80, Bb + (ll)(ldr+64)*ldb + k0 + ldc8);
            CP_COMMIT();
            asm volatile("cp.async.wait_group 1;" ::: "memory");
        } else {
            asm volatile("cp.async.wait_group 0;" ::: "memory");
        }
        __syncthreads();

        uint32_t sao = aB + st * (STG_B*2);
        uint32_t sbo = bB + st * (STG_B*2);
        #pragma unroll
        for (int ks = 0; ks < 32; ks += 16) {
            uint32_t af[4][4];
            #pragma unroll
            for (int mi = 0; mi < 4; mi++) {
                uint32_t ad = sao + (uint32_t)(aRow + mi*16)*80 + (uint32_t)(ks + aCsel)*2;
                LDSM_X4(af[mi][0], af[mi][1], af[mi][2], af[mi][3], ad);
            }
            uint32_t bf[4][2];
            #pragma unroll
            for (int nj = 0; nj < 2; nj++) {
                uint32_t bd = sbo + (uint32_t)(warpN*32 + nj*16 + bRowOff)*80
                                  + (uint32_t)(ks + bCsel)*2;
                uint32_t r0, r1, r2, r3;
                LDSM_X4(r0, r1, r2, r3, bd);
                bf[nj*2][0] = r0; bf[nj*2][1] = r1;
                bf[nj*2+1][0] = r2; bf[nj*2+1][1] = r3;
            }
            #pragma unroll
            for (int mi = 0; mi < 4; mi++)
                #pragma unroll
                for (int ni = 0; ni < 4; ni++)
                    MMA16816(acc[mi][ni], af[mi], bf[ni]);
        }
        __syncthreads();
    }

    // epilogue
    int gID = lane >> 2, tig = lane & 3;
    #pragma unroll
    for (int mi = 0; mi < 4; mi++) {
        #pragma unroll
        for (int h = 0; h < 2; h++) {
            ll row = m0 + warpM*64 + mi*16 + gID + h*8;
            ll rbase = row * (ll)ldc + (ll)z * czoff;
            #pragma unroll
            for (int ni = 0; ni < 4; ni++) {
                ll col0 = n0 + warpN*32 + ni*8 + tig*2;
                #pragma unroll
                for (int q = 0; q < 2; q++) {
                    ll col = col0 + q;
                    float v = acc[mi][ni][h*2 + q] * alpha;
                    if (bias) v += bias[col];
                    ll off = rbase + col * cstride;
                    if (out_half) {
                        ((__half*)Cv)[off] = __float2half(v);
                    } else {
                        float* cp = (float*)Cv + off;
                        if (accumulate) v += *cp;
                        *cp = v;
                    }
                }
            }
        }
    }
}

// ---------------------------------------------------------------------------
extern "C" void kernel_launch(void* const* d_in, const int* in_sizes, int n_in,
                              void* d_out, int out_size) {
    const float* x          = (const float*)d_in[0];
    const float* base_w     = (const float*)d_in[1];
    const float* base_b     = (const float*)d_in[2];
    const float* spectrum   = (const float*)d_in[3];
    const float* Blist      = (const float*)d_in[4];
    const float* gate_param = (const float*)d_in[5];
    const int*   idx_raw    = (const int*)d_in[6];
    const int*   gidx_raw   = (const int*)d_in[7];
    float* out = (float*)d_out;
    (void)in_sizes; (void)n_in; (void)out_size;

    __half *pPms, *pQns, *pW2s, *pZs, *pxh, *pxl, *pwh;
    cudaGetSymbolAddress((void**)&pPms, g_Pms);
    cudaGetSymbolAddress((void**)&pQns, g_Qns);
    cudaGetSymbolAddress((void**)&pW2s, g_W2s);
    cudaGetSymbolAddress((void**)&pZs,  g_Zs);
    cudaGetSymbolAddress((void**)&pxh,  g_xh);
    cudaGetSymbolAddress((void**)&pxl,  g_xl);
    cudaGetSymbolAddress((void**)&pwh,  g_wh);

    // 0..3: small prep
    k_decode_idx<<<1, 256>>>(idx_raw, gidx_raw);
    k_gate_m<<<16, 256>>>(gate_param);
    k_gate_w<<<ROWS, 128>>>(x);
    k_fill_trig<<<dim3(256, 2), 256>>>(spectrum);

    // 4. 150*A_p = (150/2048^2) * Pm @ Qn^T -> fp16 W2s[o2][p*2048+d2]
    tgemm<<<dim3(16, 16, 2), 256>>>(
        pPms, HALF_D, (ll)HALF_D*HALF_D,
        pQns, HALF_D, (ll)HALF_D*HALF_D,
        pW2s, DD, 1, HALF_D,
        nullptr, 150.0f/4194304.0f, 0, HALF_D, 1);

    // 5. fp16 operand prep
    k_build_z<<<(ROWS*HALF_D)/256, 256>>>(x, Blist);
    k_split_x<<<(int)(((ll)ROWS*DD)/256), 256>>>(x);
    k_cast_w<<<(int)(((ll)OO*DD)/256), 256>>>(base_w);

    // 6. base hi: out = xh @ wh^T + b    M=8192, N=4096, K=4096
    tgemm<<<dim3(64, 32, 1), 256>>>(
        pxh, DD, 0ll,
        pwh, DD, 0ll,
        out, OO, 1, 0,
        base_b, 1.0f, 0, DD, 0);

    // 7. base lo: out += xl @ wh^T       M=8192, N=4096, K=4096
    tgemm<<<dim3(64, 32, 1), 256>>>(
        pxl, DD, 0ll,
        pwh, DD, 0ll,
        out, OO, 1, 0,
        nullptr, 1.0f, 1, DD, 0);

    // 8. delta: out[row, 2n+z] += Z_z @ W2s^T   M=8192, N=2048, K=4096
    tgemm<<<dim3(64, 16, 2), 256>>>(
        pZs, DD, (ll)ROWS*DD,
        pW2s, DD, 0ll,
        out, OO, 2, 1,
        nullptr, 1.0f, 1, DD, 0);
}

// round 10
// speedup vs baseline: 1.9070x; 1.4164x over previous
#include <cuda_runtime.h>
#include <cuda_fp16.h>
#include <cstdint>

// ---------------------------------------------------------------------------
// KronFTLinear, fp16 mma.sync GEMMs (m16n8k16, f32 accum):
//   * base GEMM: single fp16 pass  out = xh @ wh + b
//       (x,w quantization -> ~3e-4 output rel err, threshold 1e-3)
//   * delta path (~2.5e-2 of output magnitude): plain fp16 (error ~1e-5)
//   * trig-GEMM scale 150 folded into stored W2 (keeps fp16 normal range)
// GEMM engine: 128x128x32 CTA tile, 8 warps (64x32), cp.async double buffer,
// 2 CTAs/SM, L2 raster swizzle.
// ---------------------------------------------------------------------------

#define DD 4096
#define OO 4096
#define HALF_D 2048
#define NFP 1000
#define ROWS 8192
#define NGATE 819

typedef long long ll;

// ---------------- device scratch (no allocation allowed) -------------------
__device__ int   g_idx32[2*NFP];
__device__ int   g_gidx32[NGATE];
__device__ float g_gate_m[2*DD];
__device__ float g_gate_w[ROWS*2];
__device__ __half g_Pms[2ll*HALF_D*HALF_D];  // trig A-factor [p][m][k]
__device__ __half g_Qns[2ll*HALF_D*HALF_D];  // trig B-factor [p][n][k]
__device__ __half g_W2s[(ll)HALF_D*DD];      // 150 * A-matrix stack (fp16)
__device__ __half g_Zs[2ll*ROWS*DD];         // gated mixed x (fp16)
__device__ __half g_xh[(ll)ROWS*DD];         // fp16 x
__device__ __half g_wh[(ll)OO*DD];           // fp16 base_w

// ---------------- PTX helpers ----------------------------------------------
__device__ __forceinline__ uint32_t smem_u32(const void* p) {
    uint32_t a;
    asm("{ .reg .u64 t; cvta.to.shared.u64 t, %1; cvt.u32.u64 %0, t; }" : "=r"(a) : "l"(p));
    return a;
}
#define CP_ASYNC16(dst, src) \
    asm volatile("cp.async.cg.shared.global [%0], [%1], 16;" :: "r"(dst), "l"(src) : "memory")
#define CP_COMMIT() asm volatile("cp.async.commit_group;" ::: "memory")

#define LDSM_X4(r0, r1, r2, r3, addr) \
    asm volatile("ldmatrix.sync.aligned.m8n8.x4.shared.b16 {%0,%1,%2,%3}, [%4];" \
        : "=r"(r0), "=r"(r1), "=r"(r2), "=r"(r3) : "r"(addr))

#define MMA16816(c, a, b) \
    asm volatile("mma.sync.aligned.m16n8k16.row.col.f32.f16.f16.f32 " \
        "{%0,%1,%2,%3}, {%4,%5,%6,%7}, {%8,%9}, {%0,%1,%2,%3};" \
        : "+f"((c)[0]), "+f"((c)[1]), "+f"((c)[2]), "+f"((c)[3]) \
        : "r"((a)[0]), "r"((a)[1]), "r"((a)[2]), "r"((a)[3]), \
          "r"((b)[0]), "r"((b)[1]))

// ---------------- index decode: sniff int32 vs int64 -----------------------
__global__ void k_decode_idx(const int* __restrict__ idx_raw,
                             const int* __restrict__ gidx_raw) {
    __shared__ int nz;
    if (threadIdx.x == 0) nz = 0;
    __syncthreads();
    for (int k = threadIdx.x; k < NFP/2; k += 256)
        if (idx_raw[2*k + 1] != 0) atomicAdd(&nz, 1);
    __syncthreads();
    bool is64 = (nz == 0);
    for (int k = threadIdx.x; k < 2*NFP; k += 256)
        g_idx32[k] = is64 ? idx_raw[2*k] : idx_raw[k];
    for (int k = threadIdx.x; k < NGATE; k += 256)
        g_gidx32[k] = is64 ? gidx_raw[2*k] : gidx_raw[k];
}

// ---------------- gate matrix ----------------------------------------------
__global__ void k_gate_m(const float* __restrict__ gate_param) {
    __shared__ float tab[DD];
    __shared__ int   gc[NGATE];
    __shared__ float gg[NGATE], gs[NGATE];
    for (int t = threadIdx.x; t < DD; t += 256)
        tab[t] = cospif(t * (1.0f/2048.0f));
    for (int k = threadIdx.x; k < NGATE; k += 256) {
        int v = g_gidx32[k];
        int r = v >> 12;
        gc[k] = v & 4095;
        float g = gate_param[k];
        gg[k] = g;
        gs[k] = r ? -g : g;
    }
    __syncthreads();
    int d = blockIdx.x * 256 + threadIdx.x;
    float a0 = 0.f, a1 = 0.f;
    for (int k = 0; k < NGATE; k++) {
        int t = (d * gc[k]) & 4095;
        float co = tab[t];
        a0 += gg[k] * co;
        a1 += gs[k] * co;
    }
    g_gate_m[d]      = a0 * (1.0f/8192.0f);
    g_gate_m[DD + d] = a1 * (1.0f/8192.0f);
}

// ---------------- gate weights ---------------------------------------------
__global__ void k_gate_w(const float* __restrict__ x) {
    int row = blockIdx.x;
    const float* xr = x + (ll)row * DD;
    float t0 = 0.f, t1 = 0.f;
    for (int d = threadIdx.x; d < DD; d += 128) {
        float xv = xr[d];
        t0 += xv * g_gate_m[d];
        t1 += xv * g_gate_m[DD + d];
    }
    __shared__ float s0[128], s1[128];
    s0[threadIdx.x] = t0; s1[threadIdx.x] = t1;
    __syncthreads();
    for (int o = 64; o > 0; o >>= 1) {
        if (threadIdx.x < o) {
            s0[threadIdx.x] += s0[threadIdx.x + o];
            s1[threadIdx.x] += s1[threadIdx.x + o];
        }
        __syncthreads();
    }
    if (threadIdx.x == 0) {
        float g1 = 1.0f / (1.0f + expf(-(s1[0] - s0[0])));
        g_gate_w[row*2 + 0] = 1.0f - g1;
        g_gate_w[row*2 + 1] = g1;
    }
}

// ---------------- trig factors, fp16 ----------------------------------------
__global__ void k_fill_trig(const float* __restrict__ spectrum) {
    __shared__ float tc[HALF_D], ts[HALF_D];
    __shared__ int   rr[NFP], cc[NFP];
    __shared__ float ss[NFP];
    int p = blockIdx.y;
    for (int t = threadIdx.x; t < HALF_D; t += 256) {
        float s, c;
        sincospif(t * (1.0f/1024.0f), &s, &c);
        tc[t] = c; ts[t] = s;
    }
    for (int k = threadIdx.x; k < NFP; k += 256) {
        int v = g_idx32[p*NFP + k];
        rr[k] = v >> 11;
        cc[k] = v & 2047;
        ss[k] = spectrum[p*NFP + k];
    }
    __syncthreads();
    int v0 = blockIdx.x * 8;
    for (int vi = 0; vi < 8; vi++) {
        int v = v0 + vi;
        ll base = ((ll)(p*HALF_D + v)) * HALF_D;
        for (int k = threadIdx.x; k < NFP; k += 256) {
            int tm = (v * rr[k]) & 2047;
            int tn = (v * cc[k]) & 2047;
            float s = ss[k];
            g_Pms[base + k]       = __float2half(s * tc[tm]);
            g_Pms[base + NFP + k] = __float2half(s * ts[tm]);
            g_Qns[base + k]       = __float2half(tc[tn]);
            g_Qns[base + NFP + k] = __float2half(-ts[tn]);
        }
        for (int k = 2*NFP + threadIdx.x; k < HALF_D; k += 256) {
            __half z = __float2half(0.f);
            g_Pms[base + k] = z;
            g_Qns[base + k] = z;
        }
    }
}

// ---------------- fp32 -> fp16 casts ----------------------------------------
__global__ void k_cast_x(const float* __restrict__ src) {
    ll i = (ll)blockIdx.x * 256 + threadIdx.x;
    g_xh[i] = __float2half(src[i]);
}
__global__ void k_cast_w(const float* __restrict__ src) {
    ll i = (ll)blockIdx.x * 256 + threadIdx.x;
    g_wh[i] = __float2half(src[i]);
}

// ---------------- Z build, fp16 ---------------------------------------------
__global__ void k_build_z(const float* __restrict__ x, const float* __restrict__ Blist) {
    ll gid = (ll)blockIdx.x * 256 + threadIdx.x;
    int row = (int)(gid >> 11);
    int d2  = (int)(gid & 2047);
    float2 xv = ((const float2*)x)[(ll)row * HALF_D + d2];
    float g0 = g_gate_w[row*2 + 0];
    float g1 = g_gate_w[row*2 + 1];
    float y00 = g0 * (Blist[0]*xv.x + Blist[1]*xv.y);   // i=0, p=0
    float y01 = g0 * (Blist[2]*xv.x + Blist[3]*xv.y);   // i=1, p=0
    float y10 = g1 * (Blist[4]*xv.x + Blist[5]*xv.y);   // i=0, p=1
    float y11 = g1 * (Blist[6]*xv.x + Blist[7]*xv.y);   // i=1, p=1
    const ll IOFF = (ll)ROWS * DD;
    ll b0 = (ll)row * DD;
    g_Zs[b0 + d2]                 = __float2half(y00);
    g_Zs[b0 + HALF_D + d2]        = __float2half(y10);
    g_Zs[IOFF + b0 + d2]          = __float2half(y01);
    g_Zs[IOFF + b0 + HALF_D + d2] = __float2half(y11);
}

// ---------------- fp16 tensor-core GEMM: C = alpha * A @ B^T (+bias)(+=C) --
// 128x128x32 CTA tile, 8 warps (64x32 warp tile), cp.async double buffer,
// 2 CTAs/SM, L2 raster swizzle (GRP m-tiles sweep all n-tiles).
// Output element (m,n,z) at C[m*ldc + n*cstride + z*czoff]; fp32 or fp16.
#define ASTR 40                // smem row stride in halves (80B, conflict-free)
#define STG_B (128*ASTR)       // half elems per stage
#define GRP 8                  // m-tiles per L2 group (all grid.x % 8 == 0)

__global__ __launch_bounds__(256, 2)
void tgemm(const __half* __restrict__ A, int lda, ll sAz,
           const __half* __restrict__ B, int ldb, ll sBz,
           void* __restrict__ Cv, int ldc, int cstride, int czoff,
           const float* __restrict__ bias, float alpha, int accumulate,
           int Kp, int out_half)
{
    __shared__ __half sA[2*STG_B];
    __shared__ __half sB[2*STG_B];
    uint32_t aB = smem_u32(sA), bB = smem_u32(sB);
    int tid = threadIdx.x, wid = tid >> 5, lane = tid & 31;
    int warpM = wid >> 2;          // 0..1  (64 rows)
    int warpN = wid & 3;           // 0..3  (32 cols)
    int z = blockIdx.z;

    // L2 raster swizzle
    int bid = blockIdx.y * gridDim.x + blockIdx.x;
    int tpg = GRP * gridDim.y;
    int grp = bid / tpg;
    int rem = bid - grp * tpg;
    int mt  = grp * GRP + (rem % GRP);
    int nt  = rem / GRP;

    ll m0 = (ll)mt * 128;
    ll n0 = (ll)nt * 128;
    const __half* Ab = A + (ll)z*sAz + m0*lda;
    const __half* Bb = B + (ll)z*sBz + n0*ldb;

    float acc[4][4][4];
    #pragma unroll
    for (int i = 0; i < 4; i++)
        #pragma unroll
        for (int j = 0; j < 4; j++)
            #pragma unroll
            for (int q = 0; q < 4; q++) acc[i][j][q] = 0.f;

    int ldr = tid >> 2;
    int ldc8 = (tid & 3) * 8;

    int aRow = warpM*64 + (lane & 15);
    int aCsel = (lane >> 4) * 8;
    int bRowOff = (lane & 7) + ((lane >> 4) << 3);
    int bCsel = ((lane >> 3) & 1) * 8;

    int NP = Kp >> 5;

    {
        uint32_t da = aB + ldr*80 + ldc8*2;
        uint32_t db = bB + ldr*80 + ldc8*2;
        CP_ASYNC16(da,        Ab + (ll)ldr*lda + ldc8);
        CP_ASYNC16(db,        Bb + (ll)ldr*ldb + ldc8);
        CP_ASYNC16(da + 64*80, Ab + (ll)(ldr+64)*lda + ldc8);
        CP_ASYNC16(db + 64*80, Bb + (ll)(ldr+64)*ldb + ldc8);
        CP_COMMIT();
    }

    for (int kc = 0; kc < NP; kc++) {
        int st = kc & 1;
        if (kc + 1 < NP) {
            int k0 = (kc + 1) * 32;
            uint32_t so = ((kc + 1) & 1) * (STG_B*2);
            uint32_t da = aB + so + ldr*80 + ldc8*2;
            uint32_t db = bB + so + ldr*80 + ldc8*2;
            CP_ASYNC16(da,        Ab + (ll)ldr*lda + k0 + ldc8);
            CP_ASYNC16(db,        Bb + (ll)ldr*ldb + k0 + ldc8);
            CP_ASYNC16(da + 64*80, Ab + (ll)(ldr+64)*lda + k0 + ldc8);
            CP_ASYNC16(db + 64*80, Bb + (ll)(ldr+64)*ldb + k0 + ldc8);
            CP_COMMIT();
            asm volatile("cp.async.wait_group 1;" ::: "memory");
        } else {
            asm volatile("cp.async.wait_group 0;" ::: "memory");
        }
        __syncthreads();

        uint32_t sao = aB + st * (STG_B*2);
        uint32_t sbo = bB + st * (STG_B*2);
        #pragma unroll
        for (int ks = 0; ks < 32; ks += 16) {
            uint32_t af[4][4];
            #pragma unroll
            for (int mi = 0; mi < 4; mi++) {
                uint32_t ad = sao + (uint32_t)(aRow + mi*16)*80 + (uint32_t)(ks + aCsel)*2;
                LDSM_X4(af[mi][0], af[mi][1], af[mi][2], af[mi][3], ad);
            }
            uint32_t bf[4][2];
            #pragma unroll
            for (int nj = 0; nj < 2; nj++) {
                uint32_t bd = sbo + (uint32_t)(warpN*32 + nj*16 + bRowOff)*80
                                  + (uint32_t)(ks + bCsel)*2;
                uint32_t r0, r1, r2, r3;
                LDSM_X4(r0, r1, r2, r3, bd);
                bf[nj*2][0] = r0; bf[nj*2][1] = r1;
                bf[nj*2+1][0] = r2; bf[nj*2+1][1] = r3;
            }
            #pragma unroll
            for (int mi = 0; mi < 4; mi++)
                #pragma unroll
                for (int ni = 0; ni < 4; ni++)
                    MMA16816(acc[mi][ni], af[mi], bf[ni]);
        }
        __syncthreads();
    }

    // epilogue
    int gID = lane >> 2, tig = lane & 3;
    #pragma unroll
    for (int mi = 0; mi < 4; mi++) {
        #pragma unroll
        for (int h = 0; h < 2; h++) {
            ll row = m0 + warpM*64 + mi*16 + gID + h*8;
            ll rbase = row * (ll)ldc + (ll)z * czoff;
            #pragma unroll
            for (int ni = 0; ni < 4; ni++) {
                ll col0 = n0 + warpN*32 + ni*8 + tig*2;
                #pragma unroll
                for (int q = 0; q < 2; q++) {
                    ll col = col0 + q;
                    float v = acc[mi][ni][h*2 + q] * alpha;
                    if (bias) v += bias[col];
                    ll off = rbase + col * cstride;
                    if (out_half) {
                        ((__half*)Cv)[off] = __float2half(v);
                    } else {
                        float* cp = (float*)Cv + off;
                        if (accumulate) v += *cp;
                        *cp = v;
                    }
                }
            }
        }
    }
}

// ---------------------------------------------------------------------------
extern "C" void kernel_launch(void* const* d_in, const int* in_sizes, int n_in,
                              void* d_out, int out_size) {
    const float* x          = (const float*)d_in[0];
    const float* base_w     = (const float*)d_in[1];
    const float* base_b     = (const float*)d_in[2];
    const float* spectrum   = (const float*)d_in[3];
    const float* Blist      = (const float*)d_in[4];
    const float* gate_param = (const float*)d_in[5];
    const int*   idx_raw    = (const int*)d_in[6];
    const int*   gidx_raw   = (const int*)d_in[7];
    float* out = (float*)d_out;
    (void)in_sizes; (void)n_in; (void)out_size;

    __half *pPms, *pQns, *pW2s, *pZs, *pxh, *pwh;
    cudaGetSymbolAddress((void**)&pPms, g_Pms);
    cudaGetSymbolAddress((void**)&pQns, g_Qns);
    cudaGetSymbolAddress((void**)&pW2s, g_W2s);
    cudaGetSymbolAddress((void**)&pZs,  g_Zs);
    cudaGetSymbolAddress((void**)&pxh,  g_xh);
    cudaGetSymbolAddress((void**)&pwh,  g_wh);

    // 0..3: small prep
    k_decode_idx<<<1, 256>>>(idx_raw, gidx_raw);
    k_gate_m<<<16, 256>>>(gate_param);
    k_gate_w<<<ROWS, 128>>>(x);
    k_fill_trig<<<dim3(256, 2), 256>>>(spectrum);

    // 4. 150*A_p = (150/2048^2) * Pm @ Qn^T -> fp16 W2s[o2][p*2048+d2]
    tgemm<<<dim3(16, 16, 2), 256>>>(
        pPms, HALF_D, (ll)HALF_D*HALF_D,
        pQns, HALF_D, (ll)HALF_D*HALF_D,
        pW2s, DD, 1, HALF_D,
        nullptr, 150.0f/4194304.0f, 0, HALF_D, 1);

    // 5. fp16 operand prep
    k_build_z<<<(ROWS*HALF_D)/256, 256>>>(x, Blist);
    k_cast_x<<<(int)(((ll)ROWS*DD)/256), 256>>>(x);
    k_cast_w<<<(int)(((ll)OO*DD)/256), 256>>>(base_w);

    // 6. base: out = xh @ wh^T + b    M=8192, N=4096, K=4096
    tgemm<<<dim3(64, 32, 1), 256>>>(
        pxh, DD, 0ll,
        pwh, DD, 0ll,
        out, OO, 1, 0,
        base_b, 1.0f, 0, DD, 0);

    // 7. delta: out[row, 2n+z] += Z_z @ W2s^T   M=8192, N=2048, K=4096
    tgemm<<<dim3(64, 16, 2), 256>>>(
        pZs, DD, (ll)ROWS*DD,
        pW2s, DD, 0ll,
        out, OO, 2, 1,
        nullptr, 1.0f, 1, DD, 0);
}

// round 11
// speedup vs baseline: 2.2014x; 1.1544x over previous
#include <cuda_runtime.h>
#include <cuda_fp16.h>
#include <cstdint>

// ---------------------------------------------------------------------------
// KronFTLinear, fp16 mma.sync GEMMs (m16n8k16, f32 accum):
//   * base GEMM: single fp16 pass  out = xh @ wh + b   (~3e-4 rel err)
//   * delta path (~2.5e-2 of output magnitude): plain fp16
//   * trig-GEMM scale 150 folded into stored W2
// GEMM engine (R11): 128x128x32 CTA tile, 4 warps of 64x64 (halves smem
// crossbar traffic per MAC vs 8x(64x32)), 128 threads, cp.async double
// buffer, 2 CTAs/SM, L2 raster swizzle.
// ---------------------------------------------------------------------------

#define DD 4096
#define OO 4096
#define HALF_D 2048
#define NFP 1000
#define ROWS 8192
#define NGATE 819

typedef long long ll;

// ---------------- device scratch (no allocation allowed) -------------------
__device__ int   g_idx32[2*NFP];
__device__ int   g_gidx32[NGATE];
__device__ float g_gate_m[2*DD];
__device__ float g_gate_w[ROWS*2];
__device__ __half g_Pms[2ll*HALF_D*HALF_D];  // trig A-factor [p][m][k]
__device__ __half g_Qns[2ll*HALF_D*HALF_D];  // trig B-factor [p][n][k]
__device__ __half g_W2s[(ll)HALF_D*DD];      // 150 * A-matrix stack (fp16)
__device__ __half g_Zs[2ll*ROWS*DD];         // gated mixed x (fp16)
__device__ __half g_xh[(ll)ROWS*DD];         // fp16 x
__device__ __half g_wh[(ll)OO*DD];           // fp16 base_w

// ---------------- PTX helpers ----------------------------------------------
__device__ __forceinline__ uint32_t smem_u32(const void* p) {
    uint32_t a;
    asm("{ .reg .u64 t; cvta.to.shared.u64 t, %1; cvt.u32.u64 %0, t; }" : "=r"(a) : "l"(p));
    return a;
}
#define CP_ASYNC16(dst, src) \
    asm volatile("cp.async.cg.shared.global [%0], [%1], 16;" :: "r"(dst), "l"(src) : "memory")
#define CP_COMMIT() asm volatile("cp.async.commit_group;" ::: "memory")

#define LDSM_X4(r0, r1, r2, r3, addr) \
    asm volatile("ldmatrix.sync.aligned.m8n8.x4.shared.b16 {%0,%1,%2,%3}, [%4];" \
        : "=r"(r0), "=r"(r1), "=r"(r2), "=r"(r3) : "r"(addr))

#define MMA16816(c, a, b) \
    asm volatile("mma.sync.aligned.m16n8k16.row.col.f32.f16.f16.f32 " \
        "{%0,%1,%2,%3}, {%4,%5,%6,%7}, {%8,%9}, {%0,%1,%2,%3};" \
        : "+f"((c)[0]), "+f"((c)[1]), "+f"((c)[2]), "+f"((c)[3]) \
        : "r"((a)[0]), "r"((a)[1]), "r"((a)[2]), "r"((a)[3]), \
          "r"((b)[0]), "r"((b)[1]))

// ---------------- index decode: sniff int32 vs int64 -----------------------
__global__ void k_decode_idx(const int* __restrict__ idx_raw,
                             const int* __restrict__ gidx_raw) {
    __shared__ int nz;
    if (threadIdx.x == 0) nz = 0;
    __syncthreads();
    for (int k = threadIdx.x; k < NFP/2; k += 256)
        if (idx_raw[2*k + 1] != 0) atomicAdd(&nz, 1);
    __syncthreads();
    bool is64 = (nz == 0);
    for (int k = threadIdx.x; k < 2*NFP; k += 256)
        g_idx32[k] = is64 ? idx_raw[2*k] : idx_raw[k];
    for (int k = threadIdx.x; k < NGATE; k += 256)
        g_gidx32[k] = is64 ? gidx_raw[2*k] : gidx_raw[k];
}

// ---------------- gate matrix ----------------------------------------------
__global__ void k_gate_m(const float* __restrict__ gate_param) {
    __shared__ float tab[DD];
    __shared__ int   gc[NGATE];
    __shared__ float gg[NGATE], gs[NGATE];
    for (int t = threadIdx.x; t < DD; t += 256)
        tab[t] = cospif(t * (1.0f/2048.0f));
    for (int k = threadIdx.x; k < NGATE; k += 256) {
        int v = g_gidx32[k];
        int r = v >> 12;
        gc[k] = v & 4095;
        float g = gate_param[k];
        gg[k] = g;
        gs[k] = r ? -g : g;
    }
    __syncthreads();
    int d = blockIdx.x * 256 + threadIdx.x;
    float a0 = 0.f, a1 = 0.f;
    for (int k = 0; k < NGATE; k++) {
        int t = (d * gc[k]) & 4095;
        float co = tab[t];
        a0 += gg[k] * co;
        a1 += gs[k] * co;
    }
    g_gate_m[d]      = a0 * (1.0f/8192.0f);
    g_gate_m[DD + d] = a1 * (1.0f/8192.0f);
}

// ---------------- gate weights (+ fused fp16 cast of x) --------------------
__global__ void k_gate_w(const float* __restrict__ x) {
    int row = blockIdx.x;
    const float* xr = x + (ll)row * DD;
    __half* xhr = g_xh + (ll)row * DD;
    float t0 = 0.f, t1 = 0.f;
    for (int d = threadIdx.x; d < DD; d += 128) {
        float xv = xr[d];
        xhr[d] = __float2half(xv);
        t0 += xv * g_gate_m[d];
        t1 += xv * g_gate_m[DD + d];
    }
    __shared__ float s0[128], s1[128];
    s0[threadIdx.x] = t0; s1[threadIdx.x] = t1;
    __syncthreads();
    for (int o = 64; o > 0; o >>= 1) {
        if (threadIdx.x < o) {
            s0[threadIdx.x] += s0[threadIdx.x + o];
            s1[threadIdx.x] += s1[threadIdx.x + o];
        }
        __syncthreads();
    }
    if (threadIdx.x == 0) {
        float g1 = 1.0f / (1.0f + expf(-(s1[0] - s0[0])));
        g_gate_w[row*2 + 0] = 1.0f - g1;
        g_gate_w[row*2 + 1] = g1;
    }
}

// ---------------- trig factors, fp16 ----------------------------------------
__global__ void k_fill_trig(const float* __restrict__ spectrum) {
    __shared__ float tc[HALF_D], ts[HALF_D];
    __shared__ int   rr[NFP], cc[NFP];
    __shared__ float ss[NFP];
    int p = blockIdx.y;
    for (int t = threadIdx.x; t < HALF_D; t += 256) {
        float s, c;
        sincospif(t * (1.0f/1024.0f), &s, &c);
        tc[t] = c; ts[t] = s;
    }
    for (int k = threadIdx.x; k < NFP; k += 256) {
        int v = g_idx32[p*NFP + k];
        rr[k] = v >> 11;
        cc[k] = v & 2047;
        ss[k] = spectrum[p*NFP + k];
    }
    __syncthreads();
    int v0 = blockIdx.x * 8;
    for (int vi = 0; vi < 8; vi++) {
        int v = v0 + vi;
        ll base = ((ll)(p*HALF_D + v)) * HALF_D;
        for (int k = threadIdx.x; k < NFP; k += 256) {
            int tm = (v * rr[k]) & 2047;
            int tn = (v * cc[k]) & 2047;
            float s = ss[k];
            g_Pms[base + k]       = __float2half(s * tc[tm]);
            g_Pms[base + NFP + k] = __float2half(s * ts[tm]);
            g_Qns[base + k]       = __float2half(tc[tn]);
            g_Qns[base + NFP + k] = __float2half(-ts[tn]);
        }
        for (int k = 2*NFP + threadIdx.x; k < HALF_D; k += 256) {
            __half z = __float2half(0.f);
            g_Pms[base + k] = z;
            g_Qns[base + k] = z;
        }
    }
}

// ---------------- fp32 w -> fp16 --------------------------------------------
__global__ void k_cast_w(const float* __restrict__ src) {
    ll i = (ll)blockIdx.x * 256 + threadIdx.x;
    g_wh[i] = __float2half(src[i]);
}

// ---------------- Z build, fp16 ---------------------------------------------
__global__ void k_build_z(const float* __restrict__ x, const float* __restrict__ Blist) {
    ll gid = (ll)blockIdx.x * 256 + threadIdx.x;
    int row = (int)(gid >> 11);
    int d2  = (int)(gid & 2047);
    float2 xv = ((const float2*)x)[(ll)row * HALF_D + d2];
    float g0 = g_gate_w[row*2 + 0];
    float g1 = g_gate_w[row*2 + 1];
    float y00 = g0 * (Blist[0]*xv.x + Blist[1]*xv.y);   // i=0, p=0
    float y01 = g0 * (Blist[2]*xv.x + Blist[3]*xv.y);   // i=1, p=0
    float y10 = g1 * (Blist[4]*xv.x + Blist[5]*xv.y);   // i=0, p=1
    float y11 = g1 * (Blist[6]*xv.x + Blist[7]*xv.y);   // i=1, p=1
    const ll IOFF = (ll)ROWS * DD;
    ll b0 = (ll)row * DD;
    g_Zs[b0 + d2]                 = __float2half(y00);
    g_Zs[b0 + HALF_D + d2]        = __float2half(y10);
    g_Zs[IOFF + b0 + d2]          = __float2half(y01);
    g_Zs[IOFF + b0 + HALF_D + d2] = __float2half(y11);
}

// ---------------- fp16 tensor-core GEMM: C = alpha * A @ B^T (+bias)(+=C) --
// 128x128x32 CTA tile, 4 warps (2x2) of 64x64, 128 threads, cp.async double
// buffer, 2 CTAs/SM, L2 raster swizzle (GRP m-tiles sweep all n-tiles).
// Output element (m,n,z) at C[m*ldc + n*cstride + z*czoff]; fp32 or fp16.
#define ASTR 40                // smem row stride in halves (80B, conflict-free)
#define STG_B (128*ASTR)       // half elems per stage
#define GRP 8                  // m-tiles per L2 group (all grid.x % 8 == 0)

__global__ __launch_bounds__(128, 2)
void tgemm(const __half* __restrict__ A, int lda, ll sAz,
           const __half* __restrict__ B, int ldb, ll sBz,
           void* __restrict__ Cv, int ldc, int cstride, int czoff,
           const float* __restrict__ bias, float alpha, int accumulate,
           int Kp, int out_half)
{
    __shared__ __half sA[2*STG_B];
    __shared__ __half sB[2*STG_B];
    uint32_t aB = smem_u32(sA), bB = smem_u32(sB);
    int tid = threadIdx.x, wid = tid >> 5, lane = tid & 31;
    int warpM = wid >> 1;          // 0..1  (64 rows)
    int warpN = wid & 1;           // 0..1  (64 cols)
    int z = blockIdx.z;

    // L2 raster swizzle
    int bid = blockIdx.y * gridDim.x + blockIdx.x;
    int tpg = GRP * gridDim.y;
    int grp = bid / tpg;
    int rem = bid - grp * tpg;
    int mt  = grp * GRP + (rem % GRP);
    int nt  = rem / GRP;

    ll m0 = (ll)mt * 128;
    ll n0 = (ll)nt * 128;
    const __half* Ab = A + (ll)z*sAz + m0*lda;
    const __half* Bb = B + (ll)z*sBz + n0*ldb;

    float acc[4][8][4];
    #pragma unroll
    for (int i = 0; i < 4; i++)
        #pragma unroll
        for (int j = 0; j < 8; j++)
            #pragma unroll
            for (int q = 0; q < 4; q++) acc[i][j][q] = 0.f;

    int ldr = tid >> 2;            // 0..31
    int ldc8 = (tid & 3) * 8;      // 0,8,16,24

    int aRow = warpM*64 + (lane & 15);
    int aCsel = (lane >> 4) * 8;
    int bRowOff = (lane & 7) + ((lane >> 4) << 3);
    int bCsel = ((lane >> 3) & 1) * 8;

    int NP = Kp >> 5;

    // loader: 128 threads, 4 row-batches of 32 for each of A and B
    #define TG_LOAD(stg_off, k0) do {                                          \
        uint32_t _da = aB + (stg_off) + (uint32_t)ldr*80 + (uint32_t)ldc8*2;   \
        uint32_t _db = bB + (stg_off) + (uint32_t)ldr*80 + (uint32_t)ldc8*2;   \
        _Pragma("unroll")                                                      \
        for (int _h = 0; _h < 4; _h++) {                                       \
            CP_ASYNC16(_da + _h*32*80, Ab + (ll)(ldr + _h*32)*lda + (k0) + ldc8); \
            CP_ASYNC16(_db + _h*32*80, Bb + (ll)(ldr + _h*32)*ldb + (k0) + ldc8); \
        }                                                                      \
        CP_COMMIT();                                                           \
    } while (0)

    TG_LOAD(0, 0);

    for (int kc = 0; kc < NP; kc++) {
        int st = kc & 1;
        if (kc + 1 < NP) {
            TG_LOAD(((kc + 1) & 1) * (STG_B*2), (kc + 1) * 32);
            asm volatile("cp.async.wait_group 1;" ::: "memory");
        } else {
            asm volatile("cp.async.wait_group 0;" ::: "memory");
        }
        __syncthreads();

        uint32_t sao = aB + st * (STG_B*2);
        uint32_t sbo = bB + st * (STG_B*2);
        #pragma unroll
        for (int ks = 0; ks < 32; ks += 16) {
            uint32_t af[4][4];
            #pragma unroll
            for (int mi = 0; mi < 4; mi++) {
                uint32_t ad = sao + (uint32_t)(aRow + mi*16)*80 + (uint32_t)(ks + aCsel)*2;
                LDSM_X4(af[mi][0], af[mi][1], af[mi][2], af[mi][3], ad);
            }
            uint32_t bf[8][2];
            #pragma unroll
            for (int nj = 0; nj < 4; nj++) {
                uint32_t bd = sbo + (uint32_t)(warpN*64 + nj*16 + bRowOff)*80
                                  + (uint32_t)(ks + bCsel)*2;
                uint32_t r0, r1, r2, r3;
                LDSM_X4(r0, r1, r2, r3, bd);
                bf[nj*2][0] = r0;   bf[nj*2][1] = r1;
                bf[nj*2+1][0] = r2; bf[nj*2+1][1] = r3;
            }
            #pragma unroll
            for (int mi = 0; mi < 4; mi++)
                #pragma unroll
                for (int ni = 0; ni < 8; ni++)
                    MMA16816(acc[mi][ni], af[mi], bf[ni]);
        }
        __syncthreads();
    }

    // epilogue
    int gID = lane >> 2, tig = lane & 3;
    #pragma unroll
    for (int mi = 0; mi < 4; mi++) {
        #pragma unroll
        for (int h = 0; h < 2; h++) {
            ll row = m0 + warpM*64 + mi*16 + gID + h*8;
            ll rbase = row * (ll)ldc + (ll)z * czoff;
            #pragma unroll
            for (int ni = 0; ni < 8; ni++) {
                ll col0 = n0 + warpN*64 + ni*8 + tig*2;
                #pragma unroll
                for (int q = 0; q < 2; q++) {
                    ll col = col0 + q;
                    float v = acc[mi][ni][h*2 + q] * alpha;
                    if (bias) v += bias[col];
                    ll off = rbase + col * cstride;
                    if (out_half) {
                        ((__half*)Cv)[off] = __float2half(v);
                    } else {
                        float* cp = (float*)Cv + off;
                        if (accumulate) v += *cp;
                        *cp = v;
                    }
                }
            }
        }
    }
    #undef TG_LOAD
}

// ---------------------------------------------------------------------------
extern "C" void kernel_launch(void* const* d_in, const int* in_sizes, int n_in,
                              void* d_out, int out_size) {
    const float* x          = (const float*)d_in[0];
    const float* base_w     = (const float*)d_in[1];
    const float* base_b     = (const float*)d_in[2];
    const float* spectrum   = (const float*)d_in[3];
    const float* Blist      = (const float*)d_in[4];
    const float* gate_param = (const float*)d_in[5];
    const int*   idx_raw    = (const int*)d_in[6];
    const int*   gidx_raw   = (const int*)d_in[7];
    float* out = (float*)d_out;
    (void)in_sizes; (void)n_in; (void)out_size;

    __half *pPms, *pQns, *pW2s, *pZs, *pxh, *pwh;
    cudaGetSymbolAddress((void**)&pPms, g_Pms);
    cudaGetSymbolAddress((void**)&pQns, g_Qns);
    cudaGetSymbolAddress((void**)&pW2s, g_W2s);
    cudaGetSymbolAddress((void**)&pZs,  g_Zs);
    cudaGetSymbolAddress((void**)&pxh,  g_xh);
    cudaGetSymbolAddress((void**)&pwh,  g_wh);

    // 0..3: small prep
    k_decode_idx<<<1, 256>>>(idx_raw, gidx_raw);
    k_gate_m<<<16, 256>>>(gate_param);
    k_gate_w<<<ROWS, 128>>>(x);          // also writes fp16 x
    k_fill_trig<<<dim3(256, 2), 256>>>(spectrum);

    // 4. 150*A_p = (150/2048^2) * Pm @ Qn^T -> fp16 W2s[o2][p*2048+d2]
    tgemm<<<dim3(16, 16, 2), 128>>>(
        pPms, HALF_D, (ll)HALF_D*HALF_D,
        pQns, HALF_D, (ll)HALF_D*HALF_D,
        pW2s, DD, 1, HALF_D,
        nullptr, 150.0f/4194304.0f, 0, HALF_D, 1);

    // 5. fp16 operand prep
    k_build_z<<<(ROWS*HALF_D)/256, 256>>>(x, Blist);
    k_cast_w<<<(int)(((ll)OO*DD)/256), 256>>>(base_w);

    // 6. base: out = xh @ wh^T + b    M=8192, N=4096, K=4096
    tgemm<<<dim3(64, 32, 1), 128>>>(
        pxh, DD, 0ll,
        pwh, DD, 0ll,
        out, OO, 1, 0,
        base_b, 1.0f, 0, DD, 0);

    // 7. delta: out[row, 2n+z] += Z_z @ W2s^T   M=8192, N=2048, K=4096
    tgemm<<<dim3(64, 16, 2), 128>>>(
        pZs, DD, (ll)ROWS*DD,
        pW2s, DD, 0ll,
        out, OO, 2, 1,
        nullptr, 1.0f, 1, DD, 0);
}

// round 12
// speedup vs baseline: 2.3899x; 1.0856x over previous
#include <cuda_runtime.h>
#include <cuda_fp16.h>
#include <cstdint>

// ---------------------------------------------------------------------------
// KronFTLinear, fp16 mma.sync GEMMs (m16n8k16, f32 accum):
//   * base GEMM: single fp16 pass  out = xh @ wh + b   (~3e-4 rel err)
//   * delta path (~2.5e-2 of output magnitude): plain fp16
//   * trig-GEMM scale 150 folded into stored W2
// GEMM engine (R12): 128x128x32 CTA tile, 4 warps of 64x64, 128 threads,
// 3-stage cp.async pipeline with ONE __syncthreads per chunk, 2 CTAs/SM
// (60KB dynamic smem each), L2 raster swizzle.
// Prep (R12): gate-weights + fp16-cast + Z-build fused into one row-resident
// pass over x.
// ---------------------------------------------------------------------------

#define DD 4096
#define OO 4096
#define HALF_D 2048
#define NFP 1000
#define ROWS 8192
#define NGATE 819

typedef long long ll;

// ---------------- device scratch (no allocation allowed) -------------------
__device__ int   g_idx32[2*NFP];
__device__ int   g_gidx32[NGATE];
__device__ float g_gate_m[2*DD];
__device__ __half g_Pms[2ll*HALF_D*HALF_D];  // trig A-factor [p][m][k]
__device__ __half g_Qns[2ll*HALF_D*HALF_D];  // trig B-factor [p][n][k]
__device__ __half g_W2s[(ll)HALF_D*DD];      // 150 * A-matrix stack (fp16)
__device__ __half g_Zs[2ll*ROWS*DD];         // gated mixed x (fp16)
__device__ __half g_xh[(ll)ROWS*DD];         // fp16 x
__device__ __half g_wh[(ll)OO*DD];           // fp16 base_w

// ---------------- PTX helpers ----------------------------------------------
__device__ __forceinline__ uint32_t smem_u32(const void* p) {
    uint32_t a;
    asm("{ .reg .u64 t; cvta.to.shared.u64 t, %1; cvt.u32.u64 %0, t; }" : "=r"(a) : "l"(p));
    return a;
}
#define CP_ASYNC16(dst, src) \
    asm volatile("cp.async.cg.shared.global [%0], [%1], 16;" :: "r"(dst), "l"(src) : "memory")
#define CP_COMMIT() asm volatile("cp.async.commit_group;" ::: "memory")

#define LDSM_X4(r0, r1, r2, r3, addr) \
    asm volatile("ldmatrix.sync.aligned.m8n8.x4.shared.b16 {%0,%1,%2,%3}, [%4];" \
        : "=r"(r0), "=r"(r1), "=r"(r2), "=r"(r3) : "r"(addr))

#define MMA16816(c, a, b) \
    asm volatile("mma.sync.aligned.m16n8k16.row.col.f32.f16.f16.f32 " \
        "{%0,%1,%2,%3}, {%4,%5,%6,%7}, {%8,%9}, {%0,%1,%2,%3};" \
        : "+f"((c)[0]), "+f"((c)[1]), "+f"((c)[2]), "+f"((c)[3]) \
        : "r"((a)[0]), "r"((a)[1]), "r"((a)[2]), "r"((a)[3]), \
          "r"((b)[0]), "r"((b)[1]))

// ---------------- index decode: sniff int32 vs int64 -----------------------
__global__ void k_decode_idx(const int* __restrict__ idx_raw,
                             const int* __restrict__ gidx_raw) {
    __shared__ int nz;
    if (threadIdx.x == 0) nz = 0;
    __syncthreads();
    for (int k = threadIdx.x; k < NFP/2; k += 256)
        if (idx_raw[2*k + 1] != 0) atomicAdd(&nz, 1);
    __syncthreads();
    bool is64 = (nz == 0);
    for (int k = threadIdx.x; k < 2*NFP; k += 256)
        g_idx32[k] = is64 ? idx_raw[2*k] : idx_raw[k];
    for (int k = threadIdx.x; k < NGATE; k += 256)
        g_gidx32[k] = is64 ? gidx_raw[2*k] : gidx_raw[k];
}

// ---------------- gate matrix ----------------------------------------------
__global__ void k_gate_m(const float* __restrict__ gate_param) {
    __shared__ float tab[DD];
    __shared__ int   gc[NGATE];
    __shared__ float gg[NGATE], gs[NGATE];
    for (int t = threadIdx.x; t < DD; t += 256)
        tab[t] = cospif(t * (1.0f/2048.0f));
    for (int k = threadIdx.x; k < NGATE; k += 256) {
        int v = g_gidx32[k];
        int r = v >> 12;
        gc[k] = v & 4095;
        float g = gate_param[k];
        gg[k] = g;
        gs[k] = r ? -g : g;
    }
    __syncthreads();
    int d = blockIdx.x * 256 + threadIdx.x;
    float a0 = 0.f, a1 = 0.f;
    for (int k = 0; k < NGATE; k++) {
        int t = (d * gc[k]) & 4095;
        float co = tab[t];
        a0 += gg[k] * co;
        a1 += gs[k] * co;
    }
    g_gate_m[d]      = a0 * (1.0f/8192.0f);
    g_gate_m[DD + d] = a1 * (1.0f/8192.0f);
}

// ---------------- fused: gate weights + fp16 x cast + Z build --------------
// One block per row. x row loaded ONCE into registers (16 float2/thread).
__global__ __launch_bounds__(128)
void k_gate_z(const float* __restrict__ x, const float* __restrict__ Blist) {
    int row = blockIdx.x;
    int tid = threadIdx.x;
    const float2* xr = (const float2*)(x + (ll)row * DD);
    const float2* gm0 = (const float2*)g_gate_m;
    const float2* gm1 = (const float2*)(g_gate_m + DD);
    __half2* xhr = (__half2*)(g_xh + (ll)row * DD);

    float2 xv[16];
    float t0 = 0.f, t1 = 0.f;
    #pragma unroll
    for (int i = 0; i < 16; i++) {
        int d2 = tid + i*128;
        float2 v = xr[d2];
        xv[i] = v;
        xhr[d2] = __floats2half2_rn(v.x, v.y);
        float2 m0 = gm0[d2], m1 = gm1[d2];
        t0 += v.x*m0.x + v.y*m0.y;
        t1 += v.x*m1.x + v.y*m1.y;
    }

    __shared__ float s0[128], s1[128];
    __shared__ float sg[2];
    s0[tid] = t0; s1[tid] = t1;
    __syncthreads();
    for (int o = 64; o > 0; o >>= 1) {
        if (tid < o) { s0[tid] += s0[tid + o]; s1[tid] += s1[tid + o]; }
        __syncthreads();
    }
    if (tid == 0) {
        float g1 = 1.0f / (1.0f + expf(-(s1[0] - s0[0])));
        sg[0] = 1.0f - g1;
        sg[1] = g1;
    }
    __syncthreads();
    float g0 = sg[0], g1 = sg[1];

    float b0 = Blist[0], b1 = Blist[1], b2 = Blist[2], b3 = Blist[3];
    float b4 = Blist[4], b5 = Blist[5], b6 = Blist[6], b7 = Blist[7];
    const ll IOFF = (ll)ROWS * DD;
    ll base = (ll)row * DD;
    #pragma unroll
    for (int i = 0; i < 16; i++) {
        int d2 = tid + i*128;
        float xx = xv[i].x, yy = xv[i].y;
        g_Zs[base + d2]                 = __float2half(g0 * (b0*xx + b1*yy)); // i=0,p=0
        g_Zs[base + HALF_D + d2]        = __float2half(g1 * (b4*xx + b5*yy)); // i=0,p=1
        g_Zs[IOFF + base + d2]          = __float2half(g0 * (b2*xx + b3*yy)); // i=1,p=0
        g_Zs[IOFF + base + HALF_D + d2] = __float2half(g1 * (b6*xx + b7*yy)); // i=1,p=1
    }
}

// ---------------- trig factors, fp16 ----------------------------------------
__global__ void k_fill_trig(const float* __restrict__ spectrum) {
    __shared__ float tc[HALF_D], ts[HALF_D];
    __shared__ int   rr[NFP], cc[NFP];
    __shared__ float ss[NFP];
    int p = blockIdx.y;
    for (int t = threadIdx.x; t < HALF_D; t += 256) {
        float s, c;
        sincospif(t * (1.0f/1024.0f), &s, &c);
        tc[t] = c; ts[t] = s;
    }
    for (int k = threadIdx.x; k < NFP; k += 256) {
        int v = g_idx32[p*NFP + k];
        rr[k] = v >> 11;
        cc[k] = v & 2047;
        ss[k] = spectrum[p*NFP + k];
    }
    __syncthreads();
    int v0 = blockIdx.x * 8;
    for (int vi = 0; vi < 8; vi++) {
        int v = v0 + vi;
        ll base = ((ll)(p*HALF_D + v)) * HALF_D;
        for (int k = threadIdx.x; k < NFP; k += 256) {
            int tm = (v * rr[k]) & 2047;
            int tn = (v * cc[k]) & 2047;
            float s = ss[k];
            g_Pms[base + k]       = __float2half(s * tc[tm]);
            g_Pms[base + NFP + k] = __float2half(s * ts[tm]);
            g_Qns[base + k]       = __float2half(tc[tn]);
            g_Qns[base + NFP + k] = __float2half(-ts[tn]);
        }
        for (int k = 2*NFP + threadIdx.x; k < HALF_D; k += 256) {
            __half z = __float2half(0.f);
            g_Pms[base + k] = z;
            g_Qns[base + k] = z;
        }
    }
}

// ---------------- fp32 w -> fp16 --------------------------------------------
__global__ void k_cast_w(const float* __restrict__ src) {
    ll i = (ll)blockIdx.x * 256 + threadIdx.x;
    g_wh[i] = __float2half(src[i]);
}

// ---------------- fp16 tensor-core GEMM: C = alpha * A @ B^T (+bias)(+=C) --
// 128x128x32 CTA tile, 4 warps (2x2) of 64x64, 128 threads, 3-stage cp.async
// pipeline (one __syncthreads per chunk), 2 CTAs/SM, L2 raster swizzle.
// Output element (m,n,z) at C[m*ldc + n*cstride + z*czoff]; fp32 or fp16.
#define ASTR 40                 // smem row stride in halves (80B, conflict-free)
#define STAGE_BYTES 20480u      // A(10240B) + B(10240B) per stage
#define SMEM_DYN (3*STAGE_BYTES)
#define GRP 8                   // m-tiles per L2 group (all grid.x % 8 == 0)

__global__ __launch_bounds__(128, 2)
void tgemm(const __half* __restrict__ A, int lda, ll sAz,
           const __half* __restrict__ B, int ldb, ll sBz,
           void* __restrict__ Cv, int ldc, int cstride, int czoff,
           const float* __restrict__ bias, float alpha, int accumulate,
           int Kp, int out_half)
{
    extern __shared__ char smem[];
    uint32_t sbase = smem_u32(smem);
    int tid = threadIdx.x, wid = tid >> 5, lane = tid & 31;
    int warpM = wid >> 1;          // 0..1  (64 rows)
    int warpN = wid & 1;           // 0..1  (64 cols)
    int z = blockIdx.z;

    // L2 raster swizzle
    int bid = blockIdx.y * gridDim.x + blockIdx.x;
    int tpg = GRP * gridDim.y;
    int grp = bid / tpg;
    int rem = bid - grp * tpg;
    int mt  = grp * GRP + (rem % GRP);
    int nt  = rem / GRP;

    ll m0 = (ll)mt * 128;
    ll n0 = (ll)nt * 128;
    const __half* Ab = A + (ll)z*sAz + m0*lda;
    const __half* Bb = B + (ll)z*sBz + n0*ldb;

    float acc[4][8][4];
    #pragma unroll
    for (int i = 0; i < 4; i++)
        #pragma unroll
        for (int j = 0; j < 8; j++)
            #pragma unroll
            for (int q = 0; q < 4; q++) acc[i][j][q] = 0.f;

    int ldr = tid >> 2;            // 0..31
    int ldc8 = (tid & 3) * 8;      // 0,8,16,24

    int aRow = warpM*64 + (lane & 15);
    int aCsel = (lane >> 4) * 8;
    int bRowOff = (lane & 7) + ((lane >> 4) << 3);
    int bCsel = ((lane >> 3) & 1) * 8;

    int NP = Kp >> 5;

    // loader: stage s at sbase + s*STAGE_BYTES (A first 10240B, then B)
    #define TG_LOAD(stg, k0) do {                                              \
        uint32_t _sb = sbase + (uint32_t)(stg)*STAGE_BYTES;                    \
        uint32_t _da = _sb + (uint32_t)ldr*80 + (uint32_t)ldc8*2;              \
        uint32_t _db = _da + 10240u;                                           \
        _Pragma("unroll")                                                      \
        for (int _h = 0; _h < 4; _h++) {                                       \
            CP_ASYNC16(_da + _h*32*80, Ab + (ll)(ldr + _h*32)*lda + (k0) + ldc8); \
            CP_ASYNC16(_db + _h*32*80, Bb + (ll)(ldr + _h*32)*ldb + (k0) + ldc8); \
        }                                                                      \
        CP_COMMIT();                                                           \
    } while (0)

    TG_LOAD(0, 0);
    if (NP > 1) TG_LOAD(1, 32);

    int stg = 0;
    for (int kc = 0; kc < NP; kc++) {
        // chunk kc is the oldest outstanding group; ensure it has landed
        if (kc + 1 < NP) {
            asm volatile("cp.async.wait_group 1;" ::: "memory");
        } else {
            asm volatile("cp.async.wait_group 0;" ::: "memory");
        }
        __syncthreads();   // publishes chunk kc; proves all warps left stage (kc-1)%3
        if (kc + 2 < NP) {
            int ns = stg + 2; if (ns >= 3) ns -= 3;
            TG_LOAD(ns, (kc + 2) * 32);
        }

        uint32_t sao = sbase + (uint32_t)stg*STAGE_BYTES;
        uint32_t sbo = sao + 10240u;
        #pragma unroll
        for (int ks = 0; ks < 32; ks += 16) {
            uint32_t af[4][4];
            #pragma unroll
            for (int mi = 0; mi < 4; mi++) {
                uint32_t ad = sao + (uint32_t)(aRow + mi*16)*80 + (uint32_t)(ks + aCsel)*2;
                LDSM_X4(af[mi][0], af[mi][1], af[mi][2], af[mi][3], ad);
            }
            uint32_t bf[8][2];
            #pragma unroll
            for (int nj = 0; nj < 4; nj++) {
                uint32_t bd = sbo + (uint32_t)(warpN*64 + nj*16 + bRowOff)*80
                                  + (uint32_t)(ks + bCsel)*2;
                uint32_t r0, r1, r2, r3;
                LDSM_X4(r0, r1, r2, r3, bd);
                bf[nj*2][0] = r0;   bf[nj*2][1] = r1;
                bf[nj*2+1][0] = r2; bf[nj*2+1][1] = r3;
            }
            #pragma unroll
            for (int mi = 0; mi < 4; mi++)
                #pragma unroll
                for (int ni = 0; ni < 8; ni++)
                    MMA16816(acc[mi][ni], af[mi], bf[ni]);
        }
        if (++stg == 3) stg = 0;
    }

    // epilogue
    int gID = lane >> 2, tig = lane & 3;
    #pragma unroll
    for (int mi = 0; mi < 4; mi++) {
        #pragma unroll
        for (int h = 0; h < 2; h++) {
            ll row = m0 + warpM*64 + mi*16 + gID + h*8;
            ll rbase = row * (ll)ldc + (ll)z * czoff;
            #pragma unroll
            for (int ni = 0; ni < 8; ni++) {
                ll col0 = n0 + warpN*64 + ni*8 + tig*2;
                #pragma unroll
                for (int q = 0; q < 2; q++) {
                    ll col = col0 + q;
                    float v = acc[mi][ni][h*2 + q] * alpha;
                    if (bias) v += bias[col];
                    ll off = rbase + col * cstride;
                    if (out_half) {
                        ((__half*)Cv)[off] = __float2half(v);
                    } else {
                        float* cp = (float*)Cv + off;
                        if (accumulate) v += *cp;
                        *cp = v;
                    }
                }
            }
        }
    }
    #undef TG_LOAD
}

// ---------------------------------------------------------------------------
extern "C" void kernel_launch(void* const* d_in, const int* in_sizes, int n_in,
                              void* d_out, int out_size) {
    const float* x          = (const float*)d_in[0];
    const float* base_w     = (const float*)d_in[1];
    const float* base_b     = (const float*)d_in[2];
    const float* spectrum   = (const float*)d_in[3];
    const float* Blist      = (const float*)d_in[4];
    const float* gate_param = (const float*)d_in[5];
    const int*   idx_raw    = (const int*)d_in[6];
    const int*   gidx_raw   = (const int*)d_in[7];
    float* out = (float*)d_out;
    (void)in_sizes; (void)n_in; (void)out_size;

    __half *pPms, *pQns, *pW2s, *pZs, *pxh, *pwh;
    cudaGetSymbolAddress((void**)&pPms, g_Pms);
    cudaGetSymbolAddress((void**)&pQns, g_Qns);
    cudaGetSymbolAddress((void**)&pW2s, g_W2s);
    cudaGetSymbolAddress((void**)&pZs,  g_Zs);
    cudaGetSymbolAddress((void**)&pxh,  g_xh);
    cudaGetSymbolAddress((void**)&pwh,  g_wh);

    cudaFuncSetAttribute(tgemm, cudaFuncAttributeMaxDynamicSharedMemorySize, SMEM_DYN);

    // 0..3: prep
    k_decode_idx<<<1, 256>>>(idx_raw, gidx_raw);
    k_gate_m<<<16, 256>>>(gate_param);
    k_gate_z<<<ROWS, 128>>>(x, Blist);     // gate weights + fp16 x + Z planes
    k_fill_trig<<<dim3(256, 2), 256>>>(spectrum);
    k_cast_w<<<(int)(((ll)OO*DD)/256), 256>>>(base_w);

    // 4. 150*A_p = (150/2048^2) * Pm @ Qn^T -> fp16 W2s[o2][p*2048+d2]
    tgemm<<<dim3(16, 16, 2), 128, SMEM_DYN>>>(
        pPms, HALF_D, (ll)HALF_D*HALF_D,
        pQns, HALF_D, (ll)HALF_D*HALF_D,
        pW2s, DD, 1, HALF_D,
        nullptr, 150.0f/4194304.0f, 0, HALF_D, 1);

    // 5. base: out = xh @ wh^T + b    M=8192, N=4096, K=4096
    tgemm<<<dim3(64, 32, 1), 128, SMEM_DYN>>>(
        pxh, DD, 0ll,
        pwh, DD, 0ll,
        out, OO, 1, 0,
        base_b, 1.0f, 0, DD, 0);

    // 6. delta: out[row, 2n+z] += Z_z @ W2s^T   M=8192, N=2048, K=4096
    tgemm<<<dim3(64, 16, 2), 128, SMEM_DYN>>>(
        pZs, DD, (ll)ROWS*DD,
        pW2s, DD, 0ll,
        out, OO, 2, 1,
        nullptr, 1.0f, 1, DD, 0);
}

// round 13
// speedup vs baseline: 2.7320x; 1.1431x over previous
#include <cuda_runtime.h>
#include <cuda_fp16.h>
#include <cstdint>

// ---------------------------------------------------------------------------
// KronFTLinear, fp16 mma.sync GEMMs (m16n8k16, f32 accum):
//   * base+delta FUSED into one K-concat GEMM:
//       out[row, 2n+z] = [xh | Z_z] @ [whp_z | W2]^T + b     (K = 8192)
//     eliminating the fp32 read-modify-write of out and a full launch.
//   * trig-GEMM scale 150 folded into stored W2.
// GEMM engine: 128x128x32 CTA tile, 4 warps of 64x64, 128 threads, 3-stage
// cp.async pipeline (one __syncthreads per chunk), 2 CTAs/SM, L2 raster
// swizzle. Dual-source tile loader switches A/B pointers at the K split.
// ---------------------------------------------------------------------------

#define DD 4096
#define OO 4096
#define HALF_D 2048
#define NFP 1000
#define ROWS 8192
#define NGATE 819

typedef long long ll;

// ---------------- device scratch (no allocation allowed) -------------------
__device__ int   g_idx32[2*NFP];
__device__ int   g_gidx32[NGATE];
__device__ float g_gate_m[2*DD];
__device__ __half g_Pms[2ll*HALF_D*HALF_D];  // trig A-factor [p][m][k]
__device__ __half g_Qns[2ll*HALF_D*HALF_D];  // trig B-factor [p][n][k]
__device__ __half g_W2s[(ll)HALF_D*DD];      // 150 * A-matrix stack (fp16)
__device__ __half g_Zs[2ll*ROWS*DD];         // gated mixed x (fp16) [i][row][*]
__device__ __half g_xh[(ll)ROWS*DD];         // fp16 x
__device__ __half g_whp[(ll)OO*DD];          // fp16 base_w, parity-packed [z][n][k]

// ---------------- PTX helpers ----------------------------------------------
__device__ __forceinline__ uint32_t smem_u32(const void* p) {
    uint32_t a;
    asm("{ .reg .u64 t; cvta.to.shared.u64 t, %1; cvt.u32.u64 %0, t; }" : "=r"(a) : "l"(p));
    return a;
}
#define CP_ASYNC16(dst, src) \
    asm volatile("cp.async.cg.shared.global [%0], [%1], 16;" :: "r"(dst), "l"(src) : "memory")
#define CP_COMMIT() asm volatile("cp.async.commit_group;" ::: "memory")

#define LDSM_X4(r0, r1, r2, r3, addr) \
    asm volatile("ldmatrix.sync.aligned.m8n8.x4.shared.b16 {%0,%1,%2,%3}, [%4];" \
        : "=r"(r0), "=r"(r1), "=r"(r2), "=r"(r3) : "r"(addr))

#define MMA16816(c, a, b) \
    asm volatile("mma.sync.aligned.m16n8k16.row.col.f32.f16.f16.f32 " \
        "{%0,%1,%2,%3}, {%4,%5,%6,%7}, {%8,%9}, {%0,%1,%2,%3};" \
        : "+f"((c)[0]), "+f"((c)[1]), "+f"((c)[2]), "+f"((c)[3]) \
        : "r"((a)[0]), "r"((a)[1]), "r"((a)[2]), "r"((a)[3]), \
          "r"((b)[0]), "r"((b)[1]))

// ---------------- index decode: sniff int32 vs int64 -----------------------
__global__ void k_decode_idx(const int* __restrict__ idx_raw,
                             const int* __restrict__ gidx_raw) {
    __shared__ int nz;
    if (threadIdx.x == 0) nz = 0;
    __syncthreads();
    for (int k = threadIdx.x; k < NFP/2; k += 256)
        if (idx_raw[2*k + 1] != 0) atomicAdd(&nz, 1);
    __syncthreads();
    bool is64 = (nz == 0);
    for (int k = threadIdx.x; k < 2*NFP; k += 256)
        g_idx32[k] = is64 ? idx_raw[2*k] : idx_raw[k];
    for (int k = threadIdx.x; k < NGATE; k += 256)
        g_gidx32[k] = is64 ? gidx_raw[2*k] : gidx_raw[k];
}

// ---------------- gate matrix ----------------------------------------------
__global__ void k_gate_m(const float* __restrict__ gate_param) {
    __shared__ float tab[DD];
    __shared__ int   gc[NGATE];
    __shared__ float gg[NGATE], gs[NGATE];
    for (int t = threadIdx.x; t < DD; t += 256)
        tab[t] = cospif(t * (1.0f/2048.0f));
    for (int k = threadIdx.x; k < NGATE; k += 256) {
        int v = g_gidx32[k];
        int r = v >> 12;
        gc[k] = v & 4095;
        float g = gate_param[k];
        gg[k] = g;
        gs[k] = r ? -g : g;
    }
    __syncthreads();
    int d = blockIdx.x * 256 + threadIdx.x;
    float a0 = 0.f, a1 = 0.f;
    for (int k = 0; k < NGATE; k++) {
        int t = (d * gc[k]) & 4095;
        float co = tab[t];
        a0 += gg[k] * co;
        a1 += gs[k] * co;
    }
    g_gate_m[d]      = a0 * (1.0f/8192.0f);
    g_gate_m[DD + d] = a1 * (1.0f/8192.0f);
}

// ---------------- fused: gate weights + fp16 x cast + Z build --------------
__global__ __launch_bounds__(128)
void k_gate_z(const float* __restrict__ x, const float* __restrict__ Blist) {
    int row = blockIdx.x;
    int tid = threadIdx.x;
    const float2* xr = (const float2*)(x + (ll)row * DD);
    const float2* gm0 = (const float2*)g_gate_m;
    const float2* gm1 = (const float2*)(g_gate_m + DD);
    __half2* xhr = (__half2*)(g_xh + (ll)row * DD);

    float2 xv[16];
    float t0 = 0.f, t1 = 0.f;
    #pragma unroll
    for (int i = 0; i < 16; i++) {
        int d2 = tid + i*128;
        float2 v = xr[d2];
        xv[i] = v;
        xhr[d2] = __floats2half2_rn(v.x, v.y);
        float2 m0 = gm0[d2], m1 = gm1[d2];
        t0 += v.x*m0.x + v.y*m0.y;
        t1 += v.x*m1.x + v.y*m1.y;
    }

    __shared__ float s0[128], s1[128];
    __shared__ float sg[2];
    s0[tid] = t0; s1[tid] = t1;
    __syncthreads();
    for (int o = 64; o > 0; o >>= 1) {
        if (tid < o) { s0[tid] += s0[tid + o]; s1[tid] += s1[tid + o]; }
        __syncthreads();
    }
    if (tid == 0) {
        float g1 = 1.0f / (1.0f + expf(-(s1[0] - s0[0])));
        sg[0] = 1.0f - g1;
        sg[1] = g1;
    }
    __syncthreads();
    float g0 = sg[0], g1 = sg[1];

    float b0 = Blist[0], b1 = Blist[1], b2 = Blist[2], b3 = Blist[3];
    float b4 = Blist[4], b5 = Blist[5], b6 = Blist[6], b7 = Blist[7];
    const ll IOFF = (ll)ROWS * DD;
    ll base = (ll)row * DD;
    #pragma unroll
    for (int i = 0; i < 16; i++) {
        int d2 = tid + i*128;
        float xx = xv[i].x, yy = xv[i].y;
        g_Zs[base + d2]                 = __float2half(g0 * (b0*xx + b1*yy)); // i=0,p=0
        g_Zs[base + HALF_D + d2]        = __float2half(g1 * (b4*xx + b5*yy)); // i=0,p=1
        g_Zs[IOFF + base + d2]          = __float2half(g0 * (b2*xx + b3*yy)); // i=1,p=0
        g_Zs[IOFF + base + HALF_D + d2] = __float2half(g1 * (b6*xx + b7*yy)); // i=1,p=1
    }
}

// ---------------- trig factors, fp16 ----------------------------------------
__global__ void k_fill_trig(const float* __restrict__ spectrum) {
    __shared__ float tc[HALF_D], ts[HALF_D];
    __shared__ int   rr[NFP], cc[NFP];
    __shared__ float ss[NFP];
    int p = blockIdx.y;
    for (int t = threadIdx.x; t < HALF_D; t += 256) {
        float s, c;
        sincospif(t * (1.0f/1024.0f), &s, &c);
        tc[t] = c; ts[t] = s;
    }
    for (int k = threadIdx.x; k < NFP; k += 256) {
        int v = g_idx32[p*NFP + k];
        rr[k] = v >> 11;
        cc[k] = v & 2047;
        ss[k] = spectrum[p*NFP + k];
    }
    __syncthreads();
    int v0 = blockIdx.x * 8;
    for (int vi = 0; vi < 8; vi++) {
        int v = v0 + vi;
        ll base = ((ll)(p*HALF_D + v)) * HALF_D;
        for (int k = threadIdx.x; k < NFP; k += 256) {
            int tm = (v * rr[k]) & 2047;
            int tn = (v * cc[k]) & 2047;
            float s = ss[k];
            g_Pms[base + k]       = __float2half(s * tc[tm]);
            g_Pms[base + NFP + k] = __float2half(s * ts[tm]);
            g_Qns[base + k]       = __float2half(tc[tn]);
            g_Qns[base + NFP + k] = __float2half(-ts[tn]);
        }
        for (int k = 2*NFP + threadIdx.x; k < HALF_D; k += 256) {
            __half z = __float2half(0.f);
            g_Pms[base + k] = z;
            g_Qns[base + k] = z;
        }
    }
}

// ---------------- fp32 w -> fp16, parity-packed: whp[z][n][k] = w[2n+z][k] --
__global__ void k_cast_wp(const float* __restrict__ src) {
    ll i = (ll)blockIdx.x * 256 + threadIdx.x;
    int o = (int)(i >> 12);
    int k = (int)(i & 4095);
    int z = o & 1, n = o >> 1;
    g_whp[(ll)z*HALF_D*DD + (ll)n*DD + k] = __float2half(src[i]);
}

// ---------------- fp16 tensor-core GEMM with K-concat dual source ----------
// C = alpha * [A | A2] @ [B | B2]^T (+bias).  Source switches at Ksplit.
// 128x128x32 CTA tile, 4 warps (2x2) of 64x64, 128 threads, 3-stage cp.async
// (one __syncthreads per chunk), 2 CTAs/SM, L2 raster swizzle.
// Output element (m,n,z) at C[m*ldc + n*cstride + z*czoff];
// bias (if set) indexed as bias[n*cstride + z*czoff].  fp32 or fp16 out.
#define ASTR 40                 // smem row stride in halves (80B, conflict-free)
#define STAGE_BYTES 20480u      // A(10240B) + B(10240B) per stage
#define SMEM_DYN (3*STAGE_BYTES)
#define GRP 8                   // m-tiles per L2 group (all grid.x % 8 == 0)

__global__ __launch_bounds__(128, 2)
void tgemm(const __half* __restrict__ A,  int lda, ll sAz,
           const __half* __restrict__ A2, ll sA2z,
           const __half* __restrict__ B,  int ldb, ll sBz,
           const __half* __restrict__ B2, ll sB2z,
           void* __restrict__ Cv, int ldc, int cstride, int czoff,
           const float* __restrict__ bias, float alpha,
           int Kp, int Ksplit, int out_half)
{
    extern __shared__ char smem[];
    uint32_t sbase = smem_u32(smem);
    int tid = threadIdx.x, wid = tid >> 5, lane = tid & 31;
    int warpM = wid >> 1;          // 0..1  (64 rows)
    int warpN = wid & 1;           // 0..1  (64 cols)
    int z = blockIdx.z;

    // L2 raster swizzle
    int bid = blockIdx.y * gridDim.x + blockIdx.x;
    int tpg = GRP * gridDim.y;
    int grp = bid / tpg;
    int rem = bid - grp * tpg;
    int mt  = grp * GRP + (rem % GRP);
    int nt  = rem / GRP;

    ll m0 = (ll)mt * 128;
    ll n0 = (ll)nt * 128;
    const __half* Ab  = A  + (ll)z*sAz  + m0*lda;
    const __half* Ab2 = A2 + (ll)z*sA2z + m0*lda;
    const __half* Bb  = B  + (ll)z*sBz  + n0*ldb;
    const __half* Bb2 = B2 + (ll)z*sB2z + n0*ldb;

    float acc[4][8][4];
    #pragma unroll
    for (int i = 0; i < 4; i++)
        #pragma unroll
        for (int j = 0; j < 8; j++)
            #pragma unroll
            for (int q = 0; q < 4; q++) acc[i][j][q] = 0.f;

    int ldr = tid >> 2;            // 0..31
    int ldc8 = (tid & 3) * 8;      // 0,8,16,24

    int aRow = warpM*64 + (lane & 15);
    int aCsel = (lane >> 4) * 8;
    int bRowOff = (lane & 7) + ((lane >> 4) << 3);
    int bCsel = ((lane >> 3) & 1) * 8;

    int NP = Kp >> 5;

    // loader: stage s at sbase + s*STAGE_BYTES (A first 10240B, then B);
    // source pointers switch at Ksplit (k0 uniform across the CTA).
    #define TG_LOAD(stg, k0) do {                                              \
        const __half* _As; const __half* _Bs; int _ko;                         \
        if ((k0) < Ksplit) { _As = Ab;  _Bs = Bb;  _ko = (k0); }               \
        else               { _As = Ab2; _Bs = Bb2; _ko = (k0) - Ksplit; }      \
        uint32_t _sb = sbase + (uint32_t)(stg)*STAGE_BYTES;                    \
        uint32_t _da = _sb + (uint32_t)ldr*80 + (uint32_t)ldc8*2;              \
        uint32_t _db = _da + 10240u;                                           \
        _Pragma("unroll")                                                      \
        for (int _h = 0; _h < 4; _h++) {                                       \
            CP_ASYNC16(_da + _h*32*80, _As + (ll)(ldr + _h*32)*lda + _ko + ldc8); \
            CP_ASYNC16(_db + _h*32*80, _Bs + (ll)(ldr + _h*32)*ldb + _ko + ldc8); \
        }                                                                      \
        CP_COMMIT();                                                           \
    } while (0)

    TG_LOAD(0, 0);
    if (NP > 1) TG_LOAD(1, 32);

    int stg = 0;
    for (int kc = 0; kc < NP; kc++) {
        if (kc + 1 < NP) {
            asm volatile("cp.async.wait_group 1;" ::: "memory");
        } else {
            asm volatile("cp.async.wait_group 0;" ::: "memory");
        }
        __syncthreads();   // publishes chunk kc; proves all warps left stage (kc-1)%3
        if (kc + 2 < NP) {
            int ns = stg + 2; if (ns >= 3) ns -= 3;
            TG_LOAD(ns, (kc + 2) * 32);
        }

        uint32_t sao = sbase + (uint32_t)stg*STAGE_BYTES;
        uint32_t sbo = sao + 10240u;
        #pragma unroll
        for (int ks = 0; ks < 32; ks += 16) {
            uint32_t af[4][4];
            #pragma unroll
            for (int mi = 0; mi < 4; mi++) {
                uint32_t ad = sao + (uint32_t)(aRow + mi*16)*80 + (uint32_t)(ks + aCsel)*2;
                LDSM_X4(af[mi][0], af[mi][1], af[mi][2], af[mi][3], ad);
            }
            uint32_t bf[8][2];
            #pragma unroll
            for (int nj = 0; nj < 4; nj++) {
                uint32_t bd = sbo + (uint32_t)(warpN*64 + nj*16 + bRowOff)*80
                                  + (uint32_t)(ks + bCsel)*2;
                uint32_t r0, r1, r2, r3;
                LDSM_X4(r0, r1, r2, r3, bd);
                bf[nj*2][0] = r0;   bf[nj*2][1] = r1;
                bf[nj*2+1][0] = r2; bf[nj*2+1][1] = r3;
            }
            #pragma unroll
            for (int mi = 0; mi < 4; mi++)
                #pragma unroll
                for (int ni = 0; ni < 8; ni++)
                    MMA16816(acc[mi][ni], af[mi], bf[ni]);
        }
        if (++stg == 3) stg = 0;
    }

    // epilogue
    int gID = lane >> 2, tig = lane & 3;
    #pragma unroll
    for (int mi = 0; mi < 4; mi++) {
        #pragma unroll
        for (int h = 0; h < 2; h++) {
            ll row = m0 + warpM*64 + mi*16 + gID + h*8;
            ll rbase = row * (ll)ldc + (ll)z * czoff;
            #pragma unroll
            for (int ni = 0; ni < 8; ni++) {
                ll col0 = n0 + warpN*64 + ni*8 + tig*2;
                #pragma unroll
                for (int q = 0; q < 2; q++) {
                    ll col = col0 + q;
                    float v = acc[mi][ni][h*2 + q] * alpha;
                    ll coff = col * cstride + (ll)z * czoff;
                    if (bias) v += bias[coff];
                    ll off = rbase + col * cstride;
                    if (out_half) {
                        ((__half*)Cv)[off] = __float2half(v);
                    } else {
                        ((float*)Cv)[off] = v;
                    }
                }
            }
        }
    }
    #undef TG_LOAD
}

// ---------------------------------------------------------------------------
extern "C" void kernel_launch(void* const* d_in, const int* in_sizes, int n_in,
                              void* d_out, int out_size) {
    const float* x          = (const float*)d_in[0];
    const float* base_w     = (const float*)d_in[1];
    const float* base_b     = (const float*)d_in[2];
    const float* spectrum   = (const float*)d_in[3];
    const float* Blist      = (const float*)d_in[4];
    const float* gate_param = (const float*)d_in[5];
    const int*   idx_raw    = (const int*)d_in[6];
    const int*   gidx_raw   = (const int*)d_in[7];
    float* out = (float*)d_out;
    (void)in_sizes; (void)n_in; (void)out_size;

    __half *pPms, *pQns, *pW2s, *pZs, *pxh, *pwhp;
    cudaGetSymbolAddress((void**)&pPms, g_Pms);
    cudaGetSymbolAddress((void**)&pQns, g_Qns);
    cudaGetSymbolAddress((void**)&pW2s, g_W2s);
    cudaGetSymbolAddress((void**)&pZs,  g_Zs);
    cudaGetSymbolAddress((void**)&pxh,  g_xh);
    cudaGetSymbolAddress((void**)&pwhp, g_whp);

    cudaFuncSetAttribute(tgemm, cudaFuncAttributeMaxDynamicSharedMemorySize, SMEM_DYN);

    // 0..4: prep
    k_decode_idx<<<1, 256>>>(idx_raw, gidx_raw);
    k_gate_m<<<16, 256>>>(gate_param);
    k_gate_z<<<ROWS, 128>>>(x, Blist);     // gate weights + fp16 x + Z planes
    k_fill_trig<<<dim3(256, 2), 256>>>(spectrum);
    k_cast_wp<<<(int)(((ll)OO*DD)/256), 256>>>(base_w);

    // 5. 150*A_p = (150/2048^2) * Pm @ Qn^T -> fp16 W2s[o2][p*2048+d2]
    tgemm<<<dim3(16, 16, 2), 128, SMEM_DYN>>>(
        pPms, HALF_D, (ll)HALF_D*HALF_D, pPms, 0ll,
        pQns, HALF_D, (ll)HALF_D*HALF_D, pQns, 0ll,
        pW2s, DD, 1, HALF_D,
        nullptr, 150.0f/4194304.0f, HALF_D, HALF_D, 1);

    // 6. fused base+delta:
    //    out[row, 2n+z] = [xh | Z_z] @ [whp_z | W2]^T + b[2n+z]
    //    M=8192, N=2048, K=8192, batch z=2
    tgemm<<<dim3(64, 16, 2), 128, SMEM_DYN>>>(
        pxh, DD, 0ll,            pZs,  (ll)ROWS*DD,
        pwhp, DD, (ll)HALF_D*DD, pW2s, 0ll,
        out, OO, 2, 1,
        base_b, 1.0f, 2*DD, DD, 0);
}

// round 14
// speedup vs baseline: 2.7581x; 1.0095x over previous
#include <cuda_runtime.h>
#include <cuda_fp16.h>
#include <cstdint>

// ---------------------------------------------------------------------------
// KronFTLinear, fp16 mma.sync GEMMs (m16n8k16, f32 accum):
//   * base+delta FUSED into one K-concat GEMM:
//       out[row, 2n+z] = [xh | Z_z] @ [whp_z | W2]^T + b     (K = 8192)
//   * trig-GEMM scale 150 folded into stored W2.
// GEMM engine: 128x128x32 CTA tile, 4 warps of 64x64, 128 threads, 3-stage
// cp.async pipeline (one __syncthreads per chunk), 2 CTAs/SM, L2 raster
// swizzle.  R14: parity batch z is the FASTEST schedule dimension (folded
// into blockIdx.x) so parity-partner CTAs co-reside -> out write sectors
// merge in L2 and shared xh/W2 reads become L2 hits.
// ---------------------------------------------------------------------------

#define DD 4096
#define OO 4096
#define HALF_D 2048
#define NFP 1000
#define ROWS 8192
#define NGATE 819

typedef long long ll;

// ---------------- device scratch (no allocation allowed) -------------------
__device__ int   g_idx32[2*NFP];
__device__ int   g_gidx32[NGATE];
__device__ float g_gate_m[2*DD];
__device__ __half g_Pms[2ll*HALF_D*HALF_D];  // trig A-factor [p][m][k]
__device__ __half g_Qns[2ll*HALF_D*HALF_D];  // trig B-factor [p][n][k]
__device__ __half g_W2s[(ll)HALF_D*DD];      // 150 * A-matrix stack (fp16)
__device__ __half g_Zs[2ll*ROWS*DD];         // gated mixed x (fp16) [i][row][*]
__device__ __half g_xh[(ll)ROWS*DD];         // fp16 x
__device__ __half g_whp[(ll)OO*DD];          // fp16 base_w, parity-packed [z][n][k]

// ---------------- PTX helpers ----------------------------------------------
__device__ __forceinline__ uint32_t smem_u32(const void* p) {
    uint32_t a;
    asm("{ .reg .u64 t; cvta.to.shared.u64 t, %1; cvt.u32.u64 %0, t; }" : "=r"(a) : "l"(p));
    return a;
}
#define CP_ASYNC16(dst, src) \
    asm volatile("cp.async.cg.shared.global [%0], [%1], 16;" :: "r"(dst), "l"(src) : "memory")
#define CP_COMMIT() asm volatile("cp.async.commit_group;" ::: "memory")

#define LDSM_X4(r0, r1, r2, r3, addr) \
    asm volatile("ldmatrix.sync.aligned.m8n8.x4.shared.b16 {%0,%1,%2,%3}, [%4];" \
        : "=r"(r0), "=r"(r1), "=r"(r2), "=r"(r3) : "r"(addr))

#define MMA16816(c, a, b) \
    asm volatile("mma.sync.aligned.m16n8k16.row.col.f32.f16.f16.f32 " \
        "{%0,%1,%2,%3}, {%4,%5,%6,%7}, {%8,%9}, {%0,%1,%2,%3};" \
        : "+f"((c)[0]), "+f"((c)[1]), "+f"((c)[2]), "+f"((c)[3]) \
        : "r"((a)[0]), "r"((a)[1]), "r"((a)[2]), "r"((a)[3]), \
          "r"((b)[0]), "r"((b)[1]))

// ---------------- index decode: sniff int32 vs int64 -----------------------
__global__ void k_decode_idx(const int* __restrict__ idx_raw,
                             const int* __restrict__ gidx_raw) {
    __shared__ int nz;
    if (threadIdx.x == 0) nz = 0;
    __syncthreads();
    for (int k = threadIdx.x; k < NFP/2; k += 256)
        if (idx_raw[2*k + 1] != 0) atomicAdd(&nz, 1);
    __syncthreads();
    bool is64 = (nz == 0);
    for (int k = threadIdx.x; k < 2*NFP; k += 256)
        g_idx32[k] = is64 ? idx_raw[2*k] : idx_raw[k];
    for (int k = threadIdx.x; k < NGATE; k += 256)
        g_gidx32[k] = is64 ? gidx_raw[2*k] : gidx_raw[k];
}

// ---------------- gate matrix ----------------------------------------------
__global__ void k_gate_m(const float* __restrict__ gate_param) {
    __shared__ float tab[DD];
    __shared__ int   gc[NGATE];
    __shared__ float gg[NGATE], gs[NGATE];
    for (int t = threadIdx.x; t < DD; t += 256)
        tab[t] = cospif(t * (1.0f/2048.0f));
    for (int k = threadIdx.x; k < NGATE; k += 256) {
        int v = g_gidx32[k];
        int r = v >> 12;
        gc[k] = v & 4095;
        float g = gate_param[k];
        gg[k] = g;
        gs[k] = r ? -g : g;
    }
    __syncthreads();
    int d = blockIdx.x * 256 + threadIdx.x;
    float a0 = 0.f, a1 = 0.f;
    for (int k = 0; k < NGATE; k++) {
        int t = (d * gc[k]) & 4095;
        float co = tab[t];
        a0 += gg[k] * co;
        a1 += gs[k] * co;
    }
    g_gate_m[d]      = a0 * (1.0f/8192.0f);
    g_gate_m[DD + d] = a1 * (1.0f/8192.0f);
}

// ---------------- fused: gate weights + fp16 x cast + Z build --------------
__global__ __launch_bounds__(128)
void k_gate_z(const float* __restrict__ x, const float* __restrict__ Blist) {
    int row = blockIdx.x;
    int tid = threadIdx.x;
    const float2* xr = (const float2*)(x + (ll)row * DD);
    const float2* gm0 = (const float2*)g_gate_m;
    const float2* gm1 = (const float2*)(g_gate_m + DD);
    __half2* xhr = (__half2*)(g_xh + (ll)row * DD);

    float2 xv[16];
    float t0 = 0.f, t1 = 0.f;
    #pragma unroll
    for (int i = 0; i < 16; i++) {
        int d2 = tid + i*128;
        float2 v = xr[d2];
        xv[i] = v;
        xhr[d2] = __floats2half2_rn(v.x, v.y);
        float2 m0 = gm0[d2], m1 = gm1[d2];
        t0 += v.x*m0.x + v.y*m0.y;
        t1 += v.x*m1.x + v.y*m1.y;
    }

    __shared__ float s0[128], s1[128];
    __shared__ float sg[2];
    s0[tid] = t0; s1[tid] = t1;
    __syncthreads();
    for (int o = 64; o > 0; o >>= 1) {
        if (tid < o) { s0[tid] += s0[tid + o]; s1[tid] += s1[tid + o]; }
        __syncthreads();
    }
    if (tid == 0) {
        float g1 = 1.0f / (1.0f + expf(-(s1[0] - s0[0])));
        sg[0] = 1.0f - g1;
        sg[1] = g1;
    }
    __syncthreads();
    float g0 = sg[0], g1 = sg[1];

    float b0 = Blist[0], b1 = Blist[1], b2 = Blist[2], b3 = Blist[3];
    float b4 = Blist[4], b5 = Blist[5], b6 = Blist[6], b7 = Blist[7];
    const ll IOFF = (ll)ROWS * DD;
    ll base = (ll)row * DD;
    #pragma unroll
    for (int i = 0; i < 16; i++) {
        int d2 = tid + i*128;
        float xx = xv[i].x, yy = xv[i].y;
        g_Zs[base + d2]                 = __float2half(g0 * (b0*xx + b1*yy)); // i=0,p=0
        g_Zs[base + HALF_D + d2]        = __float2half(g1 * (b4*xx + b5*yy)); // i=0,p=1
        g_Zs[IOFF + base + d2]          = __float2half(g0 * (b2*xx + b3*yy)); // i=1,p=0
        g_Zs[IOFF + base + HALF_D + d2] = __float2half(g1 * (b6*xx + b7*yy)); // i=1,p=1
    }
}

// ---------------- trig factors, fp16 ----------------------------------------
__global__ void k_fill_trig(const float* __restrict__ spectrum) {
    __shared__ float tc[HALF_D], ts[HALF_D];
    __shared__ int   rr[NFP], cc[NFP];
    __shared__ float ss[NFP];
    int p = blockIdx.y;
    for (int t = threadIdx.x; t < HALF_D; t += 256) {
        float s, c;
        sincospif(t * (1.0f/1024.0f), &s, &c);
        tc[t] = c; ts[t] = s;
    }
    for (int k = threadIdx.x; k < NFP; k += 256) {
        int v = g_idx32[p*NFP + k];
        rr[k] = v >> 11;
        cc[k] = v & 2047;
        ss[k] = spectrum[p*NFP + k];
    }
    __syncthreads();
    int v0 = blockIdx.x * 8;
    for (int vi = 0; vi < 8; vi++) {
        int v = v0 + vi;
        ll base = ((ll)(p*HALF_D + v)) * HALF_D;
        for (int k = threadIdx.x; k < NFP; k += 256) {
            int tm = (v * rr[k]) & 2047;
            int tn = (v * cc[k]) & 2047;
            float s = ss[k];
            g_Pms[base + k]       = __float2half(s * tc[tm]);
            g_Pms[base + NFP + k] = __float2half(s * ts[tm]);
            g_Qns[base + k]       = __float2half(tc[tn]);
            g_Qns[base + NFP + k] = __float2half(-ts[tn]);
        }
        for (int k = 2*NFP + threadIdx.x; k < HALF_D; k += 256) {
            __half z = __float2half(0.f);
            g_Pms[base + k] = z;
            g_Qns[base + k] = z;
        }
    }
}

// ---------------- fp32 w -> fp16, parity-packed: whp[z][n][k] = w[2n+z][k] --
__global__ void k_cast_wp(const float* __restrict__ src) {
    ll i = (ll)blockIdx.x * 256 + threadIdx.x;
    int o = (int)(i >> 12);
    int k = (int)(i & 4095);
    int z = o & 1, n = o >> 1;
    g_whp[(ll)z*HALF_D*DD + (ll)n*DD + k] = __float2half(src[i]);
}

// ---------------- fp16 tensor-core GEMM with K-concat dual source ----------
// C = alpha * [A | A2] @ [B | B2]^T (+bias).  Source switches at Ksplit.
// 128x128x32 CTA tile, 4 warps (2x2) of 64x64, 128 threads, 3-stage cp.async
// (one __syncthreads per chunk), 2 CTAs/SM, L2 raster swizzle.
// Batch z is folded into blockIdx.x (z = rawbid & zmask, FASTEST dim) so
// parity partners co-reside.  Output (m,n,z) at C[m*ldc + n*cstride + z*czoff];
// bias (if set) indexed as bias[n*cstride + z*czoff].  fp32 or fp16 out.
#define ASTR 40                 // smem row stride in halves (80B, conflict-free)
#define STAGE_BYTES 20480u      // A(10240B) + B(10240B) per stage
#define SMEM_DYN (3*STAGE_BYTES)
#define GRP 8                   // m-tiles per L2 group (all m-tile counts % 8 == 0)

__global__ __launch_bounds__(128, 2)
void tgemm(const __half* __restrict__ A,  int lda, ll sAz,
           const __half* __restrict__ A2, ll sA2z,
           const __half* __restrict__ B,  int ldb, ll sBz,
           const __half* __restrict__ B2, ll sB2z,
           void* __restrict__ Cv, int ldc, int cstride, int czoff,
           const float* __restrict__ bias, float alpha,
           int Kp, int Ksplit, int zshift, int out_half)
{
    extern __shared__ char smem[];
    uint32_t sbase = smem_u32(smem);
    int tid = threadIdx.x, wid = tid >> 5, lane = tid & 31;
    int warpM = wid >> 1;          // 0..1  (64 rows)
    int warpN = wid & 1;           // 0..1  (64 cols)

    // z folded into fastest launch dim; then GRP raster swizzle on tile id
    int rawbid = blockIdx.y * gridDim.x + blockIdx.x;   // x fastest in HW order
    int z   = rawbid & ((1 << zshift) - 1);
    int fl2 = rawbid >> zshift;
    int tpg = GRP * gridDim.y;
    int grp = fl2 / tpg;
    int rem = fl2 - grp * tpg;
    int mt  = grp * GRP + (rem % GRP);
    int nt  = rem / GRP;

    ll m0 = (ll)mt * 128;
    ll n0 = (ll)nt * 128;
    const __half* Ab  = A  + (ll)z*sAz  + m0*lda;
    const __half* Ab2 = A2 + (ll)z*sA2z + m0*lda;
    const __half* Bb  = B  + (ll)z*sBz  + n0*ldb;
    const __half* Bb2 = B2 + (ll)z*sB2z + n0*ldb;

    float acc[4][8][4];
    #pragma unroll
    for (int i = 0; i < 4; i++)
        #pragma unroll
        for (int j = 0; j < 8; j++)
            #pragma unroll
            for (int q = 0; q < 4; q++) acc[i][j][q] = 0.f;

    int ldr = tid >> 2;            // 0..31
    int ldc8 = (tid & 3) * 8;      // 0,8,16,24

    int aRow = warpM*64 + (lane & 15);
    int aCsel = (lane >> 4) * 8;
    int bRowOff = (lane & 7) + ((lane >> 4) << 3);
    int bCsel = ((lane >> 3) & 1) * 8;

    int NP = Kp >> 5;

    #define TG_LOAD(stg, k0) do {                                              \
        const __half* _As; const __half* _Bs; int _ko;                         \
        if ((k0) < Ksplit) { _As = Ab;  _Bs = Bb;  _ko = (k0); }               \
        else               { _As = Ab2; _Bs = Bb2; _ko = (k0) - Ksplit; }      \
        uint32_t _sb = sbase + (uint32_t)(stg)*STAGE_BYTES;                    \
        uint32_t _da = _sb + (uint32_t)ldr*80 + (uint32_t)ldc8*2;              \
        uint32_t _db = _da + 10240u;                                           \
        _Pragma("unroll")                                                      \
        for (int _h = 0; _h < 4; _h++) {                                       \
            CP_ASYNC16(_da + _h*32*80, _As + (ll)(ldr + _h*32)*lda + _ko + ldc8); \
            CP_ASYNC16(_db + _h*32*80, _Bs + (ll)(ldr + _h*32)*ldb + _ko + ldc8); \
        }                                                                      \
        CP_COMMIT();                                                           \
    } while (0)

    TG_LOAD(0, 0);
    if (NP > 1) TG_LOAD(1, 32);

    int stg = 0;
    for (int kc = 0; kc < NP; kc++) {
        if (kc + 1 < NP) {
            asm volatile("cp.async.wait_group 1;" ::: "memory");
        } else {
            asm volatile("cp.async.wait_group 0;" ::: "memory");
        }
        __syncthreads();   // publishes chunk kc; proves all warps left stage (kc-1)%3
        if (kc + 2 < NP) {
            int ns = stg + 2; if (ns >= 3) ns -= 3;
            TG_LOAD(ns, (kc + 2) * 32);
        }

        uint32_t sao = sbase + (uint32_t)stg*STAGE_BYTES;
        uint32_t sbo = sao + 10240u;
        #pragma unroll
        for (int ks = 0; ks < 32; ks += 16) {
            uint32_t af[4][4];
            #pragma unroll
            for (int mi = 0; mi < 4; mi++) {
                uint32_t ad = sao + (uint32_t)(aRow + mi*16)*80 + (uint32_t)(ks + aCsel)*2;
                LDSM_X4(af[mi][0], af[mi][1], af[mi][2], af[mi][3], ad);
            }
            uint32_t bf[8][2];
            #pragma unroll
            for (int nj = 0; nj < 4; nj++) {
                uint32_t bd = sbo + (uint32_t)(warpN*64 + nj*16 + bRowOff)*80
                                  + (uint32_t)(ks + bCsel)*2;
                uint32_t r0, r1, r2, r3;
                LDSM_X4(r0, r1, r2, r3, bd);
                bf[nj*2][0] = r0;   bf[nj*2][1] = r1;
                bf[nj*2+1][0] = r2; bf[nj*2+1][1] = r3;
            }
            #pragma unroll
            for (int mi = 0; mi < 4; mi++)
                #pragma unroll
                for (int ni = 0; ni < 8; ni++)
                    MMA16816(acc[mi][ni], af[mi], bf[ni]);
        }
        if (++stg == 3) stg = 0;
    }

    // epilogue
    int gID = lane >> 2, tig = lane & 3;
    #pragma unroll
    for (int mi = 0; mi < 4; mi++) {
        #pragma unroll
        for (int h = 0; h < 2; h++) {
            ll row = m0 + warpM*64 + mi*16 + gID + h*8;
            ll rbase = row * (ll)ldc + (ll)z * czoff;
            #pragma unroll
            for (int ni = 0; ni < 8; ni++) {
                ll col0 = n0 + warpN*64 + ni*8 + tig*2;
                #pragma unroll
                for (int q = 0; q < 2; q++) {
                    ll col = col0 + q;
                    float v = acc[mi][ni][h*2 + q] * alpha;
                    ll coff = col * cstride + (ll)z * czoff;
                    if (bias) v += bias[coff];
                    ll off = rbase + col * cstride;
                    if (out_half) {
                        ((__half*)Cv)[off] = __float2half(v);
                    } else {
                        ((float*)Cv)[off] = v;
                    }
                }
            }
        }
    }
    #undef TG_LOAD
}

// ---------------------------------------------------------------------------
extern "C" void kernel_launch(void* const* d_in, const int* in_sizes, int n_in,
                              void* d_out, int out_size) {
    const float* x          = (const float*)d_in[0];
    const float* base_w     = (const float*)d_in[1];
    const float* base_b     = (const float*)d_in[2];
    const float* spectrum   = (const float*)d_in[3];
    const float* Blist      = (const float*)d_in[4];
    const float* gate_param = (const float*)d_in[5];
    const int*   idx_raw    = (const int*)d_in[6];
    const int*   gidx_raw   = (const int*)d_in[7];
    float* out = (float*)d_out;
    (void)in_sizes; (void)n_in; (void)out_size;

    __half *pPms, *pQns, *pW2s, *pZs, *pxh, *pwhp;
    cudaGetSymbolAddress((void**)&pPms, g_Pms);
    cudaGetSymbolAddress((void**)&pQns, g_Qns);
    cudaGetSymbolAddress((void**)&pW2s, g_W2s);
    cudaGetSymbolAddress((void**)&pZs,  g_Zs);
    cudaGetSymbolAddress((void**)&pxh,  g_xh);
    cudaGetSymbolAddress((void**)&pwhp, g_whp);

    cudaFuncSetAttribute(tgemm, cudaFuncAttributeMaxDynamicSharedMemorySize, SMEM_DYN);

    // 0..4: prep
    k_decode_idx<<<1, 256>>>(idx_raw, gidx_raw);
    k_gate_m<<<16, 256>>>(gate_param);
    k_gate_z<<<ROWS, 128>>>(x, Blist);     // gate weights + fp16 x + Z planes
    k_fill_trig<<<dim3(256, 2), 256>>>(spectrum);
    k_cast_wp<<<(int)(((ll)OO*DD)/256), 256>>>(base_w);

    // 5. 150*A_p = (150/2048^2) * Pm @ Qn^T -> fp16 W2s[o2][p*2048+d2]
    //    M=N=2048, K=2048, zbat=2 folded into grid.x
    tgemm<<<dim3(32, 16, 1), 128, SMEM_DYN>>>(
        pPms, HALF_D, (ll)HALF_D*HALF_D, pPms, 0ll,
        pQns, HALF_D, (ll)HALF_D*HALF_D, pQns, 0ll,
        pW2s, DD, 1, HALF_D,
        nullptr, 150.0f/4194304.0f, HALF_D, HALF_D, 1, 1);

    // 6. fused base+delta:
    //    out[row, 2n+z] = [xh | Z_z] @ [whp_z | W2]^T + b[2n+z]
    //    M=8192, N=2048, K=8192, zbat=2 folded into grid.x (parity-adjacent)
    tgemm<<<dim3(128, 16, 1), 128, SMEM_DYN>>>(
        pxh, DD, 0ll,            pZs,  (ll)ROWS*DD,
        pwhp, DD, (ll)HALF_D*DD, pW2s, 0ll,
        out, OO, 2, 1,
        base_b, 1.0f, 2*DD, DD, 1, 0);
}